// round 3
// baseline (speedup 1.0000x reference)
#include <cuda_runtime.h>
#include <cuda_bf16.h>

// Problem constants
#define BB   2
#define TT   2048
#define DD   1024
#define HH   16
#define HD   64
#define MM   (BB*TT)      // 4096
#define KK   1024
#define SCALING 0.125f    // 64^-0.5

// Scratch (device globals; no allocation allowed)
__device__ float g_q[BB*HH*TT*HD];   // [b,h,t,d]
__device__ float g_k[BB*HH*TT*HD];
__device__ float g_v[BB*HH*TT*HD];
__device__ float g_ao[MM*DD];        // attention output, [b*T+t][h*64+d]

// ---------------------------------------------------------------------------
// GEMM: C[M,N] = A[M,K] @ W[N,K]^T + bias, optionally scaled, optionally
// written in [b,h,t,d] layout. M=4096, N=1024, K=1024 fixed.
// 128x128 tile, BK=16, 256 threads, 8x8 per-thread register tile.
// ---------------------------------------------------------------------------
#define GBM 128
#define GBN 128
#define GBK 16

__global__ __launch_bounds__(256) void gemm_bias_kernel(
    const float* __restrict__ A, const float* __restrict__ W,
    const float* __restrict__ bias, float* __restrict__ out,
    float scale, int bhtd)
{
    __shared__ float As[GBK][GBM];
    __shared__ float Bs[GBK][GBN];

    const int tid = threadIdx.x;
    const int m0 = blockIdx.y * GBM;
    const int n0 = blockIdx.x * GBN;
    const int tx = tid & 15;
    const int ty = tid >> 4;

    float acc[8][8];
    #pragma unroll
    for (int i = 0; i < 8; i++)
        #pragma unroll
        for (int j = 0; j < 8; j++) acc[i][j] = 0.0f;

    for (int k0 = 0; k0 < KK; k0 += GBK) {
        // Load A tile and W tile (both K-major) transposed into smem.
        #pragma unroll
        for (int it = 0; it < 2; it++) {
            int e   = tid + it * 256;        // 0..511
            int row = e >> 2;                // 0..127
            int kq  = (e & 3) * 4;           // 0,4,8,12
            float4 a4 = *(const float4*)(A + (size_t)(m0 + row) * KK + k0 + kq);
            As[kq + 0][row] = a4.x;
            As[kq + 1][row] = a4.y;
            As[kq + 2][row] = a4.z;
            As[kq + 3][row] = a4.w;
            float4 b4 = *(const float4*)(W + (size_t)(n0 + row) * KK + k0 + kq);
            Bs[kq + 0][row] = b4.x;
            Bs[kq + 1][row] = b4.y;
            Bs[kq + 2][row] = b4.z;
            Bs[kq + 3][row] = b4.w;
        }
        __syncthreads();

        #pragma unroll
        for (int kk = 0; kk < GBK; kk++) {
            float a[8], b[8];
            *(float4*)(a)     = *(const float4*)&As[kk][ty * 8];
            *(float4*)(a + 4) = *(const float4*)&As[kk][ty * 8 + 4];
            *(float4*)(b)     = *(const float4*)&Bs[kk][tx * 8];
            *(float4*)(b + 4) = *(const float4*)&Bs[kk][tx * 8 + 4];
            #pragma unroll
            for (int i = 0; i < 8; i++)
                #pragma unroll
                for (int j = 0; j < 8; j++)
                    acc[i][j] += a[i] * b[j];
        }
        __syncthreads();
    }

    // Epilogue: +bias, *scale, write either [b,h,t,d] or row-major [M,N]
    #pragma unroll
    for (int i = 0; i < 8; i++) {
        int m = m0 + ty * 8 + i;
        int bb = m >> 11;         // /T
        int t  = m & (TT - 1);
        #pragma unroll
        for (int j = 0; j < 8; j++) {
            int n = n0 + tx * 8 + j;
            float val = (acc[i][j] + bias[n]) * scale;
            if (bhtd) {
                int h = n >> 6, d = n & 63;
                out[(((size_t)(bb * HH + h) * TT) + t) * HD + d] = val;
            } else {
                out[(size_t)m * DD + n] = val;
            }
        }
    }
}

// ---------------------------------------------------------------------------
// Fused attention: per (q-tile of 64, head, batch), flash-style over K/V
// tiles of 64. e = f * exp(S); running row-sum; O accumulated; normalized at
// the end. No running-max needed: scores have sigma ~0.4, exp never overflows.
// ---------------------------------------------------------------------------
#define SPAD 68   // smem row stride (floats), multiple of 4 for float4 loads

__global__ __launch_bounds__(256) void attn_kernel(const float* __restrict__ F)
{
    extern __shared__ float smf[];
    float* Qs  = smf;                 // [64][SPAD] transposed: Qs[d][row]
    float* Ks  = Qs + 64 * SPAD;      // Ks[d][col]
    float* Vs  = Ks + 64 * SPAD;      // Vs[s][d]
    float* Es  = Vs + 64 * SPAD;      // Es[row][s]
    float* red = Es + 64 * SPAD;      // [64][17]

    const int h  = blockIdx.y;
    const int b  = blockIdx.z;
    const int q0 = blockIdx.x * 64;
    const int tid = threadIdx.x;
    const int tx = tid & 15;
    const int ty = tid >> 4;

    const float* qb = g_q + (size_t)(b * HH + h) * TT * HD;
    const float* kb = g_k + (size_t)(b * HH + h) * TT * HD;
    const float* vb = g_v + (size_t)(b * HH + h) * TT * HD;
    const float* fb = F + (size_t)b * TT * TT;

    // Load Q tile transposed into smem (once per CTA)
    #pragma unroll
    for (int it = 0; it < 4; it++) {
        int e   = tid + it * 256;     // 0..1023
        int row = e >> 4;             // 0..63
        int dq  = (e & 15) * 4;
        float4 v4 = *(const float4*)(qb + (size_t)(q0 + row) * HD + dq);
        Qs[(dq + 0) * SPAD + row] = v4.x;
        Qs[(dq + 1) * SPAD + row] = v4.y;
        Qs[(dq + 2) * SPAD + row] = v4.z;
        Qs[(dq + 3) * SPAD + row] = v4.w;
    }

    float O[4][4];
    float lsum[4] = {0.f, 0.f, 0.f, 0.f};
    #pragma unroll
    for (int i = 0; i < 4; i++)
        #pragma unroll
        for (int j = 0; j < 4; j++) O[i][j] = 0.0f;

    for (int kt = 0; kt < TT / 64; kt++) {
        const int k0 = kt * 64;
        // Load K (transposed) and V (direct) tiles
        #pragma unroll
        for (int it = 0; it < 4; it++) {
            int e   = tid + it * 256;
            int row = e >> 4;
            int dq  = (e & 15) * 4;
            float4 k4 = *(const float4*)(kb + (size_t)(k0 + row) * HD + dq);
            Ks[(dq + 0) * SPAD + row] = k4.x;
            Ks[(dq + 1) * SPAD + row] = k4.y;
            Ks[(dq + 2) * SPAD + row] = k4.z;
            Ks[(dq + 3) * SPAD + row] = k4.w;
            float4 vv = *(const float4*)(vb + (size_t)(k0 + row) * HD + dq);
            *(float4*)&Vs[row * SPAD + dq] = vv;
        }
        // Prefetch the f tile values this thread needs (latency hidden by S)
        float4 f4[4];
        #pragma unroll
        for (int i = 0; i < 4; i++)
            f4[i] = *(const float4*)(fb + (size_t)(q0 + ty * 4 + i) * TT + k0 + tx * 4);

        __syncthreads();

        // S = Q @ K^T for this 64x64 tile; thread owns rows ty*4+i, cols tx*4+j
        float S[4][4];
        #pragma unroll
        for (int i = 0; i < 4; i++)
            #pragma unroll
            for (int j = 0; j < 4; j++) S[i][j] = 0.0f;

        #pragma unroll
        for (int d = 0; d < 64; d++) {
            float4 q4 = *(const float4*)&Qs[d * SPAD + ty * 4];
            float4 k4 = *(const float4*)&Ks[d * SPAD + tx * 4];
            float qa[4] = {q4.x, q4.y, q4.z, q4.w};
            float ka[4] = {k4.x, k4.y, k4.z, k4.w};
            #pragma unroll
            for (int i = 0; i < 4; i++)
                #pragma unroll
                for (int j = 0; j < 4; j++)
                    S[i][j] += qa[i] * ka[j];
        }

        // e = f * exp(S); accumulate row sums; stage e into smem
        #pragma unroll
        for (int i = 0; i < 4; i++) {
            float fa[4] = {f4[i].x, f4[i].y, f4[i].z, f4[i].w};
            #pragma unroll
            for (int j = 0; j < 4; j++) {
                float e_ = fa[j] * __expf(S[i][j]);
                lsum[i] += e_;
                S[i][j] = e_;
            }
            *(float4*)&Es[(ty * 4 + i) * SPAD + tx * 4] =
                make_float4(S[i][0], S[i][1], S[i][2], S[i][3]);
        }
        __syncthreads();

        // O += E @ V   (contract over s; thread owns rows ty*4+i, hd cols tx*4+j)
        #pragma unroll
        for (int s4 = 0; s4 < 16; s4++) {
            float4 e4[4], vv[4];
            #pragma unroll
            for (int i = 0; i < 4; i++)
                e4[i] = *(const float4*)&Es[(ty * 4 + i) * SPAD + s4 * 4];
            #pragma unroll
            for (int r = 0; r < 4; r++)
                vv[r] = *(const float4*)&Vs[(s4 * 4 + r) * SPAD + tx * 4];
            #pragma unroll
            for (int i = 0; i < 4; i++) {
                float ea[4] = {e4[i].x, e4[i].y, e4[i].z, e4[i].w};
                #pragma unroll
                for (int r = 0; r < 4; r++) {
                    O[i][0] += ea[r] * vv[r].x;
                    O[i][1] += ea[r] * vv[r].y;
                    O[i][2] += ea[r] * vv[r].z;
                    O[i][3] += ea[r] * vv[r].w;
                }
            }
        }
        __syncthreads();
    }

    // Reduce row sums across the 16 tx threads
    #pragma unroll
    for (int i = 0; i < 4; i++)
        red[(ty * 4 + i) * 17 + tx] = lsum[i];
    __syncthreads();
    if (tid < 64) {
        float s = 0.f;
        #pragma unroll
        for (int x = 0; x < 16; x++) s += red[tid * 17 + x];
        red[tid * 17 + 16] = s;
    }
    __syncthreads();

    // Normalize and write to g_ao in [b*T+t][h*64+d] layout
    #pragma unroll
    for (int i = 0; i < 4; i++) {
        float inv = 1.0f / red[(ty * 4 + i) * 17 + 16];
        int t = q0 + ty * 4 + i;
        float* op = g_ao + (size_t)(b * TT + t) * DD + h * HD + tx * 4;
        *(float4*)op = make_float4(O[i][0] * inv, O[i][1] * inv,
                                   O[i][2] * inv, O[i][3] * inv);
    }
}

// ---------------------------------------------------------------------------
extern "C" void kernel_launch(void* const* d_in, const int* in_sizes, int n_in,
                              void* d_out, int out_size)
{
    const float* X  = (const float*)d_in[0];
    const float* F  = (const float*)d_in[1];
    const float* Wq = (const float*)d_in[2];
    const float* bq = (const float*)d_in[3];
    const float* Wk = (const float*)d_in[4];
    const float* bk = (const float*)d_in[5];
    const float* Wv = (const float*)d_in[6];
    const float* bv = (const float*)d_in[7];
    const float* Wo = (const float*)d_in[8];
    const float* bo = (const float*)d_in[9];
    float* out = (float*)d_out;

    float *q, *k, *v, *ao;
    cudaGetSymbolAddress((void**)&q,  g_q);
    cudaGetSymbolAddress((void**)&k,  g_k);
    cudaGetSymbolAddress((void**)&v,  g_v);
    cudaGetSymbolAddress((void**)&ao, g_ao);

    const int ATTN_SMEM = (4 * 64 * SPAD + 64 * 17) * 4;   // 73984 bytes
    cudaFuncSetAttribute(attn_kernel,
                         cudaFuncAttributeMaxDynamicSharedMemorySize, ATTN_SMEM);

    dim3 ggrid(DD / GBN, MM / GBM);   // (8, 32)
    gemm_bias_kernel<<<ggrid, 256>>>(X, Wq, bq, q, SCALING, 1);
    gemm_bias_kernel<<<ggrid, 256>>>(X, Wk, bk, k, 1.0f, 1);
    gemm_bias_kernel<<<ggrid, 256>>>(X, Wv, bv, v, 1.0f, 1);

    dim3 agrid(TT / 64, HH, BB);      // (32, 16, 2)
    attn_kernel<<<agrid, 256, ATTN_SMEM>>>(F);

    gemm_bias_kernel<<<ggrid, 256>>>(ao, Wo, bo, out, 1.0f, 0);
}

// round 7
// speedup vs baseline: 1.4577x; 1.4577x over previous
#include <cuda_runtime.h>
#include <cuda_bf16.h>
#include <cstdint>

// Problem constants
#define BB   2
#define TT   2048
#define DD   1024
#define HH   16
#define HD   64
#define MM   (BB*TT)      // 4096
#define KK   1024
#define SCALING 0.125f    // 64^-0.5

// Scratch (device globals; no allocation allowed)
__device__ float g_q[BB*HH*TT*HD];   // [b,h,t,d]
__device__ float g_k[BB*HH*TT*HD];
__device__ float g_v[BB*HH*TT*HD];
__device__ float g_ao[MM*DD];        // attention output, [b*T+t][h*64+d]

// bf16 split operands for tensor-core GEMMs
__device__ __nv_bfloat16 g_xhi[MM*KK],  g_xlo[MM*KK];
__device__ __nv_bfloat16 g_whi[4*KK*KK], g_wlo[4*KK*KK];
__device__ __nv_bfloat16 g_aohi[MM*KK], g_aolo[MM*KK];

// ---------------------------------------------------------------------------
// Baseline-PTX helpers (valid at .target sm_103: no tcgen05 / no 'a' features)
// ---------------------------------------------------------------------------
__device__ __forceinline__ uint32_t smem_u32(const void* p) {
    uint32_t a;
    asm("{ .reg .u64 t; cvta.to.shared.u64 t, %1; cvt.u32.u64 %0, t; }"
        : "=r"(a) : "l"(p));
    return a;
}

#define CP_ASYNC16(dst_u32, src_ptr) \
    asm volatile("cp.async.cg.shared.global [%0], [%1], 16;" \
                 :: "r"(dst_u32), "l"(src_ptr))
#define CP_COMMIT() asm volatile("cp.async.commit_group;" ::: "memory")
#define CP_WAIT1()  asm volatile("cp.async.wait_group 1;" ::: "memory")
#define CP_WAIT0()  asm volatile("cp.async.wait_group 0;" ::: "memory")

#define LDSM4(r, addr)                                                         \
    asm volatile("ldmatrix.sync.aligned.m8n8.x4.shared.b16 {%0,%1,%2,%3}, [%4];" \
        : "=r"((r)[0]), "=r"((r)[1]), "=r"((r)[2]), "=r"((r)[3]) : "r"(addr))

#define MMA16816(c, a, b0, b1)                                                 \
    asm volatile("mma.sync.aligned.m16n8k16.row.col.f32.bf16.bf16.f32 "        \
        "{%0,%1,%2,%3}, {%4,%5,%6,%7}, {%8,%9}, {%0,%1,%2,%3};"                \
        : "+f"((c)[0]), "+f"((c)[1]), "+f"((c)[2]), "+f"((c)[3])               \
        : "r"((a)[0]), "r"((a)[1]), "r"((a)[2]), "r"((a)[3]),                  \
          "r"(b0), "r"(b1))

// ---------------------------------------------------------------------------
// fp32 -> (bf16 hi, bf16 lo) split.  x ~= hi + lo with |err| <~ 2^-17 |x|
// ---------------------------------------------------------------------------
__global__ __launch_bounds__(256) void split_bf16(
    const float* __restrict__ in, __nv_bfloat16* __restrict__ hi,
    __nv_bfloat16* __restrict__ lo, int n4)
{
    int i = blockIdx.x * blockDim.x + threadIdx.x;
    if (i >= n4) return;
    float4 v = ((const float4*)in)[i];
    __nv_bfloat16 h0 = __float2bfloat16(v.x);
    __nv_bfloat16 h1 = __float2bfloat16(v.y);
    __nv_bfloat16 h2 = __float2bfloat16(v.z);
    __nv_bfloat16 h3 = __float2bfloat16(v.w);
    __nv_bfloat16 l0 = __float2bfloat16(v.x - __bfloat162float(h0));
    __nv_bfloat16 l1 = __float2bfloat16(v.y - __bfloat162float(h1));
    __nv_bfloat16 l2 = __float2bfloat16(v.z - __bfloat162float(h2));
    __nv_bfloat16 l3 = __float2bfloat16(v.w - __bfloat162float(h3));
    ((__nv_bfloat162*)hi)[2*i]   = __halves2bfloat162(h0, h1);
    ((__nv_bfloat162*)hi)[2*i+1] = __halves2bfloat162(h2, h3);
    ((__nv_bfloat162*)lo)[2*i]   = __halves2bfloat162(l0, l1);
    ((__nv_bfloat162*)lo)[2*i+1] = __halves2bfloat162(l2, l3);
}

// ---------------------------------------------------------------------------
// mma.sync GEMM:  C[M,N] = (Ahi+Alo)[M,K] @ (Whi+Wlo)[N,K]^T + bias, *scale
// 128x128 tile per CTA, 8 warps in 2(M) x 4(N): each warp 64x32.
// K-chunks of 64 bf16, double-buffered via cp.async.cg.
// 3 terms per chunk: AhWh + AhWl + AlWh, fp32 accumulation in registers.
// Smem rows padded to 144B -> conflict-free ldmatrix.
// ---------------------------------------------------------------------------
#define CH 64
#define SKB 144                      // smem row stride in bytes (64*2 + 16)
#define GTILE (128 * SKB)            // 18432 B per matrix tile
#define GSTAGE (4 * GTILE)           // Ahi,Alo,Whi,Wlo = 73728 B
#define NCHUNK (KK / CH)             // 16

__global__ __launch_bounds__(256) void gemm_mma(
    const __nv_bfloat16* __restrict__ Ahi, const __nv_bfloat16* __restrict__ Alo,
    const __nv_bfloat16* __restrict__ Whi, const __nv_bfloat16* __restrict__ Wlo,
    const float* __restrict__ bias, float* __restrict__ out,
    float scale, int bhtd)
{
    extern __shared__ char sm[];
    const int tid  = threadIdx.x;
    const int wid  = tid >> 5;
    const int lane = tid & 31;
    const int wm   = wid >> 2;        // 0..1  (M half)
    const int wn   = wid & 3;         // 0..3  (N quarter)
    const int m0 = blockIdx.y * 128;
    const int n0 = blockIdx.x * 128;

    const uint32_t sbase = smem_u32(sm);

    float acc[4][4][4];
    #pragma unroll
    for (int mi = 0; mi < 4; mi++)
        #pragma unroll
        for (int nf = 0; nf < 4; nf++)
            #pragma unroll
            for (int c = 0; c < 4; c++) acc[mi][nf][c] = 0.0f;

    auto load_chunk = [&](int k0, int stg) {
        uint32_t st = sbase + stg * GSTAGE;
        #pragma unroll
        for (int r = 0; r < 4; r++) {
            int e   = tid + r * 256;         // 0..1023
            int row = e >> 3;                // 0..127
            int c   = e & 7;                 // 16B chunk
            uint32_t d = st + row * SKB + c * 16;
            size_t ga = (size_t)(m0 + row) * KK + k0 + c * 8;
            size_t gw = (size_t)(n0 + row) * KK + k0 + c * 8;
            CP_ASYNC16(d + 0 * GTILE, (const char*)(Ahi + ga));
            CP_ASYNC16(d + 1 * GTILE, (const char*)(Alo + ga));
            CP_ASYNC16(d + 2 * GTILE, (const char*)(Whi + gw));
            CP_ASYNC16(d + 3 * GTILE, (const char*)(Wlo + gw));
        }
    };

    // ldmatrix per-lane row/col components (see fragment mapping notes):
    // A x4 frag (16x16):  matrix m = lane>>3:  row += (m&1)*8,  col += (m>>1)*8
    // B x4 frag (16n x 16k as 4 8x8): row += (m>>1)*8, col += (m&1)*8
    const int arow = wm * 64 + ((lane >> 3) & 1) * 8 + (lane & 7);
    const int acol = (lane >> 4) * 8;
    const int brow = wn * 32 + (lane >> 4) * 8 + (lane & 7);
    const int bcol = ((lane >> 3) & 1) * 8;

    auto compute_chunk = [&](int stg) {
        uint32_t st   = sbase + stg * GSTAGE;
        uint32_t aAhi = st + 0 * GTILE;
        uint32_t aAlo = st + 1 * GTILE;
        uint32_t aWhi = st + 2 * GTILE;
        uint32_t aWlo = st + 3 * GTILE;
        #pragma unroll
        for (int ks = 0; ks < 4; ks++) {
            const int kc2 = (ks * 16) * 2;
            uint32_t a[4][4], bh[2][4], bl[2][4];
            #pragma unroll
            for (int mi = 0; mi < 4; mi++)
                LDSM4(a[mi], aAhi + (arow + mi * 16) * SKB + (acol * 2 + kc2));
            #pragma unroll
            for (int p = 0; p < 2; p++)
                LDSM4(bh[p], aWhi + (brow + p * 16) * SKB + (bcol * 2 + kc2));
            // term 1: Ahi * Whi
            #pragma unroll
            for (int mi = 0; mi < 4; mi++)
                #pragma unroll
                for (int nf = 0; nf < 4; nf++)
                    MMA16816(acc[mi][nf], a[mi],
                             bh[nf >> 1][(nf & 1) * 2], bh[nf >> 1][(nf & 1) * 2 + 1]);
            #pragma unroll
            for (int p = 0; p < 2; p++)
                LDSM4(bl[p], aWlo + (brow + p * 16) * SKB + (bcol * 2 + kc2));
            // term 2: Ahi * Wlo
            #pragma unroll
            for (int mi = 0; mi < 4; mi++)
                #pragma unroll
                for (int nf = 0; nf < 4; nf++)
                    MMA16816(acc[mi][nf], a[mi],
                             bl[nf >> 1][(nf & 1) * 2], bl[nf >> 1][(nf & 1) * 2 + 1]);
            // term 3: Alo * Whi (reuse a[] registers)
            #pragma unroll
            for (int mi = 0; mi < 4; mi++)
                LDSM4(a[mi], aAlo + (arow + mi * 16) * SKB + (acol * 2 + kc2));
            #pragma unroll
            for (int mi = 0; mi < 4; mi++)
                #pragma unroll
                for (int nf = 0; nf < 4; nf++)
                    MMA16816(acc[mi][nf], a[mi],
                             bh[nf >> 1][(nf & 1) * 2], bh[nf >> 1][(nf & 1) * 2 + 1]);
        }
    };

    load_chunk(0, 0);
    CP_COMMIT();

    for (int i = 0; i < NCHUNK; i++) {
        if (i + 1 < NCHUNK) {
            load_chunk((i + 1) * CH, (i + 1) & 1);
            CP_COMMIT();
            CP_WAIT1();             // chunk i complete, chunk i+1 may be in flight
        } else {
            CP_WAIT0();
        }
        __syncthreads();
        compute_chunk(i & 1);
        __syncthreads();            // stage (i&1) may be overwritten next iter
    }

    // Epilogue: acc frag (mi,nf): c0,c1 at (row, col..col+1), c2,c3 at row+8.
    #pragma unroll
    for (int mi = 0; mi < 4; mi++) {
        #pragma unroll
        for (int nf = 0; nf < 4; nf++) {
            int r0 = m0 + wm * 64 + mi * 16 + (lane >> 2);
            int cc = n0 + wn * 32 + nf * 8 + 2 * (lane & 3);
            float b0 = bias[cc], b1 = bias[cc + 1];
            #pragma unroll
            for (int half = 0; half < 2; half++) {
                int r = r0 + half * 8;
                float2 v;
                v.x = (acc[mi][nf][half * 2 + 0] + b0) * scale;
                v.y = (acc[mi][nf][half * 2 + 1] + b1) * scale;
                if (bhtd) {
                    int bbv = r >> 11, t = r & (TT - 1);
                    int h = cc >> 6, d = cc & 63;
                    *(float2*)&out[(((size_t)(bbv * HH + h) * TT) + t) * HD + d] = v;
                } else {
                    *(float2*)&out[(size_t)r * DD + cc] = v;
                }
            }
        }
    }
}

// ---------------------------------------------------------------------------
// Fused attention (unchanged from passing R0 kernel): per (q-tile 64, head,
// batch), flash-style over K/V tiles of 64. e = f * exp(S); running row-sum.
// ---------------------------------------------------------------------------
#define SPAD 68

__global__ __launch_bounds__(256) void attn_kernel(const float* __restrict__ F)
{
    extern __shared__ float smf[];
    float* Qs  = smf;
    float* Ks  = Qs + 64 * SPAD;
    float* Vs  = Ks + 64 * SPAD;
    float* Es  = Vs + 64 * SPAD;
    float* red = Es + 64 * SPAD;

    const int h  = blockIdx.y;
    const int b  = blockIdx.z;
    const int q0 = blockIdx.x * 64;
    const int tid = threadIdx.x;
    const int tx = tid & 15;
    const int ty = tid >> 4;

    const float* qb = g_q + (size_t)(b * HH + h) * TT * HD;
    const float* kb = g_k + (size_t)(b * HH + h) * TT * HD;
    const float* vb = g_v + (size_t)(b * HH + h) * TT * HD;
    const float* fb = F + (size_t)b * TT * TT;

    #pragma unroll
    for (int it = 0; it < 4; it++) {
        int e   = tid + it * 256;
        int row = e >> 4;
        int dq  = (e & 15) * 4;
        float4 v4 = *(const float4*)(qb + (size_t)(q0 + row) * HD + dq);
        Qs[(dq + 0) * SPAD + row] = v4.x;
        Qs[(dq + 1) * SPAD + row] = v4.y;
        Qs[(dq + 2) * SPAD + row] = v4.z;
        Qs[(dq + 3) * SPAD + row] = v4.w;
    }

    float O[4][4];
    float lsum[4] = {0.f, 0.f, 0.f, 0.f};
    #pragma unroll
    for (int i = 0; i < 4; i++)
        #pragma unroll
        for (int j = 0; j < 4; j++) O[i][j] = 0.0f;

    for (int kt = 0; kt < TT / 64; kt++) {
        const int k0 = kt * 64;
        #pragma unroll
        for (int it = 0; it < 4; it++) {
            int e   = tid + it * 256;
            int row = e >> 4;
            int dq  = (e & 15) * 4;
            float4 k4 = *(const float4*)(kb + (size_t)(k0 + row) * HD + dq);
            Ks[(dq + 0) * SPAD + row] = k4.x;
            Ks[(dq + 1) * SPAD + row] = k4.y;
            Ks[(dq + 2) * SPAD + row] = k4.z;
            Ks[(dq + 3) * SPAD + row] = k4.w;
            float4 vv = *(const float4*)(vb + (size_t)(k0 + row) * HD + dq);
            *(float4*)&Vs[row * SPAD + dq] = vv;
        }
        float4 f4[4];
        #pragma unroll
        for (int i = 0; i < 4; i++)
            f4[i] = *(const float4*)(fb + (size_t)(q0 + ty * 4 + i) * TT + k0 + tx * 4);

        __syncthreads();

        float S[4][4];
        #pragma unroll
        for (int i = 0; i < 4; i++)
            #pragma unroll
            for (int j = 0; j < 4; j++) S[i][j] = 0.0f;

        #pragma unroll
        for (int d = 0; d < 64; d++) {
            float4 q4 = *(const float4*)&Qs[d * SPAD + ty * 4];
            float4 k4 = *(const float4*)&Ks[d * SPAD + tx * 4];
            float qa[4] = {q4.x, q4.y, q4.z, q4.w};
            float ka[4] = {k4.x, k4.y, k4.z, k4.w};
            #pragma unroll
            for (int i = 0; i < 4; i++)
                #pragma unroll
                for (int j = 0; j < 4; j++)
                    S[i][j] += qa[i] * ka[j];
        }

        #pragma unroll
        for (int i = 0; i < 4; i++) {
            float fa[4] = {f4[i].x, f4[i].y, f4[i].z, f4[i].w};
            #pragma unroll
            for (int j = 0; j < 4; j++) {
                float e_ = fa[j] * __expf(S[i][j]);
                lsum[i] += e_;
                S[i][j] = e_;
            }
            *(float4*)&Es[(ty * 4 + i) * SPAD + tx * 4] =
                make_float4(S[i][0], S[i][1], S[i][2], S[i][3]);
        }
        __syncthreads();

        #pragma unroll
        for (int s4 = 0; s4 < 16; s4++) {
            float4 e4[4], vv[4];
            #pragma unroll
            for (int i = 0; i < 4; i++)
                e4[i] = *(const float4*)&Es[(ty * 4 + i) * SPAD + s4 * 4];
            #pragma unroll
            for (int r = 0; r < 4; r++)
                vv[r] = *(const float4*)&Vs[(s4 * 4 + r) * SPAD + tx * 4];
            #pragma unroll
            for (int i = 0; i < 4; i++) {
                float ea[4] = {e4[i].x, e4[i].y, e4[i].z, e4[i].w};
                #pragma unroll
                for (int r = 0; r < 4; r++) {
                    O[i][0] += ea[r] * vv[r].x;
                    O[i][1] += ea[r] * vv[r].y;
                    O[i][2] += ea[r] * vv[r].z;
                    O[i][3] += ea[r] * vv[r].w;
                }
            }
        }
        __syncthreads();
    }

    #pragma unroll
    for (int i = 0; i < 4; i++)
        red[(ty * 4 + i) * 17 + tx] = lsum[i];
    __syncthreads();
    if (tid < 64) {
        float s = 0.f;
        #pragma unroll
        for (int x = 0; x < 16; x++) s += red[tid * 17 + x];
        red[tid * 17 + 16] = s;
    }
    __syncthreads();

    #pragma unroll
    for (int i = 0; i < 4; i++) {
        float inv = 1.0f / red[(ty * 4 + i) * 17 + 16];
        int t = q0 + ty * 4 + i;
        float* op = g_ao + (size_t)(b * TT + t) * DD + h * HD + tx * 4;
        *(float4*)op = make_float4(O[i][0] * inv, O[i][1] * inv,
                                   O[i][2] * inv, O[i][3] * inv);
    }
}

// ---------------------------------------------------------------------------
extern "C" void kernel_launch(void* const* d_in, const int* in_sizes, int n_in,
                              void* d_out, int out_size)
{
    const float* X  = (const float*)d_in[0];
    const float* F  = (const float*)d_in[1];
    const float* Wq = (const float*)d_in[2];
    const float* bq = (const float*)d_in[3];
    const float* Wk = (const float*)d_in[4];
    const float* bk = (const float*)d_in[5];
    const float* Wv = (const float*)d_in[6];
    const float* bv = (const float*)d_in[7];
    const float* Wo = (const float*)d_in[8];
    const float* bo = (const float*)d_in[9];
    float* out = (float*)d_out;

    float *q, *k, *v, *ao;
    __nv_bfloat16 *xhi, *xlo, *whi, *wlo, *aohi, *aolo;
    cudaGetSymbolAddress((void**)&q,    g_q);
    cudaGetSymbolAddress((void**)&k,    g_k);
    cudaGetSymbolAddress((void**)&v,    g_v);
    cudaGetSymbolAddress((void**)&ao,   g_ao);
    cudaGetSymbolAddress((void**)&xhi,  g_xhi);
    cudaGetSymbolAddress((void**)&xlo,  g_xlo);
    cudaGetSymbolAddress((void**)&whi,  g_whi);
    cudaGetSymbolAddress((void**)&wlo,  g_wlo);
    cudaGetSymbolAddress((void**)&aohi, g_aohi);
    cudaGetSymbolAddress((void**)&aolo, g_aolo);

    const int ATTN_SMEM = (4 * 64 * SPAD + 64 * 17) * 4;   // 73984 bytes
    const int GEMM_SMEM = 2 * GSTAGE;                      // 147456 bytes
    cudaFuncSetAttribute(attn_kernel,
                         cudaFuncAttributeMaxDynamicSharedMemorySize, ATTN_SMEM);
    cudaFuncSetAttribute(gemm_mma,
                         cudaFuncAttributeMaxDynamicSharedMemorySize, GEMM_SMEM);

    const int NX4 = MM * KK / 4;   // 1M float4
    const int NW4 = KK * KK / 4;   // 256K float4
    split_bf16<<<NX4 / 256, 256>>>(X,  xhi, xlo, NX4);
    split_bf16<<<NW4 / 256, 256>>>(Wq, whi + 0*KK*KK, wlo + 0*KK*KK, NW4);
    split_bf16<<<NW4 / 256, 256>>>(Wk, whi + 1*KK*KK, wlo + 1*KK*KK, NW4);
    split_bf16<<<NW4 / 256, 256>>>(Wv, whi + 2*KK*KK, wlo + 2*KK*KK, NW4);
    split_bf16<<<NW4 / 256, 256>>>(Wo, whi + 3*KK*KK, wlo + 3*KK*KK, NW4);

    dim3 ggrid(DD / 128, MM / 128);   // (8, 32)
    gemm_mma<<<ggrid, 256, GEMM_SMEM>>>(xhi, xlo, whi + 0*KK*KK, wlo + 0*KK*KK,
                                        bq, q, SCALING, 1);
    gemm_mma<<<ggrid, 256, GEMM_SMEM>>>(xhi, xlo, whi + 1*KK*KK, wlo + 1*KK*KK,
                                        bk, k, 1.0f, 1);
    gemm_mma<<<ggrid, 256, GEMM_SMEM>>>(xhi, xlo, whi + 2*KK*KK, wlo + 2*KK*KK,
                                        bv, v, 1.0f, 1);

    dim3 agrid(TT / 64, HH, BB);      // (32, 16, 2)
    attn_kernel<<<agrid, 256, ATTN_SMEM>>>(F);

    split_bf16<<<NX4 / 256, 256>>>(ao, aohi, aolo, NX4);
    gemm_mma<<<ggrid, 256, GEMM_SMEM>>>(aohi, aolo, whi + 3*KK*KK, wlo + 3*KK*KK,
                                        bo, out, 1.0f, 0);
}

// round 8
// speedup vs baseline: 2.4915x; 1.7091x over previous
#include <cuda_runtime.h>
#include <cuda_bf16.h>
#include <cstdint>

// Problem constants
#define BB   2
#define TT   2048
#define DD   1024
#define HH   16
#define HD   64
#define MM   (BB*TT)      // 4096
#define KK   1024
#define SCALING 0.125f    // 64^-0.5

// Scratch (device globals; no allocation allowed)
__device__ __nv_bfloat16 g_xhi[MM*KK],  g_xlo[MM*KK];
__device__ __nv_bfloat16 g_whi[4*KK*KK], g_wlo[4*KK*KK];
__device__ __nv_bfloat16 g_qhi[BB*HH*TT*HD], g_qlo[BB*HH*TT*HD];
__device__ __nv_bfloat16 g_khi[BB*HH*TT*HD], g_klo[BB*HH*TT*HD];
__device__ __nv_bfloat16 g_vhi[BB*HH*TT*HD], g_vlo[BB*HH*TT*HD];
__device__ __nv_bfloat16 g_aohi[MM*KK], g_aolo[MM*KK];

// ---------------------------------------------------------------------------
// Baseline-PTX helpers (valid at .target sm_103)
// ---------------------------------------------------------------------------
__device__ __forceinline__ uint32_t smem_u32(const void* p) {
    uint32_t a;
    asm("{ .reg .u64 t; cvta.to.shared.u64 t, %1; cvt.u32.u64 %0, t; }"
        : "=r"(a) : "l"(p));
    return a;
}

#define CP_ASYNC16(dst_u32, src_ptr) \
    asm volatile("cp.async.cg.shared.global [%0], [%1], 16;" \
                 :: "r"(dst_u32), "l"(src_ptr))
#define CP_COMMIT() asm volatile("cp.async.commit_group;" ::: "memory")
#define CP_WAIT1()  asm volatile("cp.async.wait_group 1;" ::: "memory")
#define CP_WAIT0()  asm volatile("cp.async.wait_group 0;" ::: "memory")

#define LDSM4(r, addr)                                                         \
    asm volatile("ldmatrix.sync.aligned.m8n8.x4.shared.b16 {%0,%1,%2,%3}, [%4];" \
        : "=r"((r)[0]), "=r"((r)[1]), "=r"((r)[2]), "=r"((r)[3]) : "r"(addr))

#define LDSM4T(r, addr)                                                        \
    asm volatile("ldmatrix.sync.aligned.m8n8.x4.trans.shared.b16 {%0,%1,%2,%3}, [%4];" \
        : "=r"((r)[0]), "=r"((r)[1]), "=r"((r)[2]), "=r"((r)[3]) : "r"(addr))

#define MMA16816(c, a, b0, b1)                                                 \
    asm volatile("mma.sync.aligned.m16n8k16.row.col.f32.bf16.bf16.f32 "        \
        "{%0,%1,%2,%3}, {%4,%5,%6,%7}, {%8,%9}, {%0,%1,%2,%3};"                \
        : "+f"((c)[0]), "+f"((c)[1]), "+f"((c)[2]), "+f"((c)[3])               \
        : "r"((a)[0]), "r"((a)[1]), "r"((a)[2]), "r"((a)[3]),                  \
          "r"(b0), "r"(b1))

__device__ __forceinline__ void split1(float x, __nv_bfloat16& h, __nv_bfloat16& l) {
    h = __float2bfloat16(x);
    l = __float2bfloat16(x - __bfloat162float(h));
}

// ---------------------------------------------------------------------------
// fp32 -> (bf16 hi, bf16 lo) split kernel (for X and the 4 weight matrices)
// ---------------------------------------------------------------------------
__global__ __launch_bounds__(256) void split_bf16(
    const float* __restrict__ in, __nv_bfloat16* __restrict__ hi,
    __nv_bfloat16* __restrict__ lo, int n4)
{
    int i = blockIdx.x * blockDim.x + threadIdx.x;
    if (i >= n4) return;
    float4 v = ((const float4*)in)[i];
    __nv_bfloat16 h0, h1, h2, h3, l0, l1, l2, l3;
    split1(v.x, h0, l0); split1(v.y, h1, l1);
    split1(v.z, h2, l2); split1(v.w, h3, l3);
    ((__nv_bfloat162*)hi)[2*i]   = __halves2bfloat162(h0, h1);
    ((__nv_bfloat162*)hi)[2*i+1] = __halves2bfloat162(h2, h3);
    ((__nv_bfloat162*)lo)[2*i]   = __halves2bfloat162(l0, l1);
    ((__nv_bfloat162*)lo)[2*i+1] = __halves2bfloat162(l2, l3);
}

// ---------------------------------------------------------------------------
// mma.sync GEMM (as R7), epilogue writes either fp32 (bhtd=0, to outF) or
// bf16 hi/lo split pairs in [b,h,t,d] layout (bhtd=1, to outHi/outLo).
// ---------------------------------------------------------------------------
#define CH 64
#define SKB 144
#define GTILE (128 * SKB)
#define GSTAGE (4 * GTILE)
#define NCHUNK (KK / CH)

__global__ __launch_bounds__(256) void gemm_mma(
    const __nv_bfloat16* __restrict__ Ahi, const __nv_bfloat16* __restrict__ Alo,
    const __nv_bfloat16* __restrict__ Whi, const __nv_bfloat16* __restrict__ Wlo,
    const float* __restrict__ bias, float* __restrict__ outF,
    __nv_bfloat16* __restrict__ outHi, __nv_bfloat16* __restrict__ outLo,
    float scale, int bhtd)
{
    extern __shared__ char sm[];
    const int tid  = threadIdx.x;
    const int wid  = tid >> 5;
    const int lane = tid & 31;
    const int wm   = wid >> 2;
    const int wn   = wid & 3;
    const int m0 = blockIdx.y * 128;
    const int n0 = blockIdx.x * 128;

    const uint32_t sbase = smem_u32(sm);

    float acc[4][4][4];
    #pragma unroll
    for (int mi = 0; mi < 4; mi++)
        #pragma unroll
        for (int nf = 0; nf < 4; nf++)
            #pragma unroll
            for (int c = 0; c < 4; c++) acc[mi][nf][c] = 0.0f;

    auto load_chunk = [&](int k0, int stg) {
        uint32_t st = sbase + stg * GSTAGE;
        #pragma unroll
        for (int r = 0; r < 4; r++) {
            int e   = tid + r * 256;
            int row = e >> 3;
            int c   = e & 7;
            uint32_t d = st + row * SKB + c * 16;
            size_t ga = (size_t)(m0 + row) * KK + k0 + c * 8;
            size_t gw = (size_t)(n0 + row) * KK + k0 + c * 8;
            CP_ASYNC16(d + 0 * GTILE, (const char*)(Ahi + ga));
            CP_ASYNC16(d + 1 * GTILE, (const char*)(Alo + ga));
            CP_ASYNC16(d + 2 * GTILE, (const char*)(Whi + gw));
            CP_ASYNC16(d + 3 * GTILE, (const char*)(Wlo + gw));
        }
    };

    const int arow = wm * 64 + ((lane >> 3) & 1) * 8 + (lane & 7);
    const int acol = (lane >> 4) * 8;
    const int brow = wn * 32 + (lane >> 4) * 8 + (lane & 7);
    const int bcol = ((lane >> 3) & 1) * 8;

    auto compute_chunk = [&](int stg) {
        uint32_t st   = sbase + stg * GSTAGE;
        uint32_t aAhi = st + 0 * GTILE;
        uint32_t aAlo = st + 1 * GTILE;
        uint32_t aWhi = st + 2 * GTILE;
        uint32_t aWlo = st + 3 * GTILE;
        #pragma unroll
        for (int ks = 0; ks < 4; ks++) {
            const int kc2 = (ks * 16) * 2;
            uint32_t a[4][4], bh[2][4], bl[2][4];
            #pragma unroll
            for (int mi = 0; mi < 4; mi++)
                LDSM4(a[mi], aAhi + (arow + mi * 16) * SKB + (acol * 2 + kc2));
            #pragma unroll
            for (int p = 0; p < 2; p++)
                LDSM4(bh[p], aWhi + (brow + p * 16) * SKB + (bcol * 2 + kc2));
            #pragma unroll
            for (int mi = 0; mi < 4; mi++)
                #pragma unroll
                for (int nf = 0; nf < 4; nf++)
                    MMA16816(acc[mi][nf], a[mi],
                             bh[nf >> 1][(nf & 1) * 2], bh[nf >> 1][(nf & 1) * 2 + 1]);
            #pragma unroll
            for (int p = 0; p < 2; p++)
                LDSM4(bl[p], aWlo + (brow + p * 16) * SKB + (bcol * 2 + kc2));
            #pragma unroll
            for (int mi = 0; mi < 4; mi++)
                #pragma unroll
                for (int nf = 0; nf < 4; nf++)
                    MMA16816(acc[mi][nf], a[mi],
                             bl[nf >> 1][(nf & 1) * 2], bl[nf >> 1][(nf & 1) * 2 + 1]);
            #pragma unroll
            for (int mi = 0; mi < 4; mi++)
                LDSM4(a[mi], aAlo + (arow + mi * 16) * SKB + (acol * 2 + kc2));
            #pragma unroll
            for (int mi = 0; mi < 4; mi++)
                #pragma unroll
                for (int nf = 0; nf < 4; nf++)
                    MMA16816(acc[mi][nf], a[mi],
                             bh[nf >> 1][(nf & 1) * 2], bh[nf >> 1][(nf & 1) * 2 + 1]);
        }
    };

    load_chunk(0, 0);
    CP_COMMIT();

    for (int i = 0; i < NCHUNK; i++) {
        if (i + 1 < NCHUNK) {
            load_chunk((i + 1) * CH, (i + 1) & 1);
            CP_COMMIT();
            CP_WAIT1();
        } else {
            CP_WAIT0();
        }
        __syncthreads();
        compute_chunk(i & 1);
        __syncthreads();
    }

    #pragma unroll
    for (int mi = 0; mi < 4; mi++) {
        #pragma unroll
        for (int nf = 0; nf < 4; nf++) {
            int r0 = m0 + wm * 64 + mi * 16 + (lane >> 2);
            int cc = n0 + wn * 32 + nf * 8 + 2 * (lane & 3);
            float b0 = bias[cc], b1 = bias[cc + 1];
            #pragma unroll
            for (int half = 0; half < 2; half++) {
                int r = r0 + half * 8;
                float vx = (acc[mi][nf][half * 2 + 0] + b0) * scale;
                float vy = (acc[mi][nf][half * 2 + 1] + b1) * scale;
                if (bhtd) {
                    int bbv = r >> 11, t = r & (TT - 1);
                    int hh = cc >> 6, d = cc & 63;
                    size_t idx = (((size_t)(bbv * HH + hh) * TT) + t) * HD + d;
                    __nv_bfloat16 h0, h1, l0, l1;
                    split1(vx, h0, l0); split1(vy, h1, l1);
                    *(__nv_bfloat162*)&outHi[idx] = __halves2bfloat162(h0, h1);
                    *(__nv_bfloat162*)&outLo[idx] = __halves2bfloat162(l0, l1);
                } else {
                    float2 v; v.x = vx; v.y = vy;
                    *(float2*)&outF[(size_t)r * DD + cc] = v;
                }
            }
        }
    }
}

// ---------------------------------------------------------------------------
// Tensor-core fused attention. Per CTA: 128 q-rows of one (head, batch).
// Loop over 16 kv tiles of 128. S = QK^T via 3-term bf16-split mma;
// e = f*exp(S) in fp32 frags; P split to bf16 hi/lo in smem; O += P·V via
// 3-term mma with V B-frags from ldmatrix.trans. Normalize at end; emit
// attention output directly as bf16 hi/lo split for the final projection.
//
// smem (bytes): Qhi 0, Qlo 18432, Khi 36864, Klo 55296,
//               V[2 stages]{hi,lo} 73728 + stg*36864 (+18432 for lo),
//               Phi 147456, Plo 182272, rsum 217088..219136
// ---------------------------------------------------------------------------
#define AT_SMEM 219136

__global__ __launch_bounds__(256) void attn_mma(const float* __restrict__ F)
{
    extern __shared__ char sm[];
    const int tid = threadIdx.x, lane = tid & 31, wid = tid >> 5;
    const int wm = wid >> 2, wn = wid & 3;
    const int h = blockIdx.y, b = blockIdx.z;
    const int q0 = blockIdx.x * 128;

    const uint32_t S0 = smem_u32(sm);
    const uint32_t sQh = S0,          sQl = S0 + 18432;
    const uint32_t sKh = S0 + 36864,  sKl = S0 + 55296;
    const uint32_t sVb = S0 + 73728;             // + stg*36864, lo at +18432
    const uint32_t sPh = S0 + 147456, sPl = S0 + 182272;
    float* rsum = (float*)(sm + 217088);         // [4][128]

    const size_t hoff = ((size_t)(b * HH + h)) * TT * HD;
    const __nv_bfloat16 *qh = g_qhi + hoff, *ql = g_qlo + hoff;
    const __nv_bfloat16 *kh = g_khi + hoff, *kl = g_klo + hoff;
    const __nv_bfloat16 *vh = g_vhi + hoff, *vl = g_vlo + hoff;
    const float* fb = F + (size_t)b * TT * TT;

    auto load64 = [&](uint32_t dst, const __nv_bfloat16* src) {
        #pragma unroll
        for (int r = 0; r < 4; r++) {
            int e = tid + r * 256;
            int row = e >> 3, c = e & 7;
            CP_ASYNC16(dst + row * 144 + c * 16, src + (size_t)row * HD + c * 8);
        }
    };

    // preload Q (persistent) + K/V tile 0
    load64(sQh, qh + (size_t)q0 * HD);
    load64(sQl, ql + (size_t)q0 * HD);
    load64(sKh, kh);
    load64(sKl, kl);
    load64(sVb, vh);
    load64(sVb + 18432, vl);
    CP_COMMIT();

    // fragment lane geometry (verified in R7's gemm)
    const int arow  = wm * 64 + ((lane >> 3) & 1) * 8 + (lane & 7);
    const int acol2 = ((lane >> 4) * 8) * 2;                  // bytes
    const int brow  = wn * 32 + (lane >> 4) * 8 + (lane & 7);
    const int bcol2 = (((lane >> 3) & 1) * 8) * 2;
    const int vrow0 = ((lane >> 3) & 1) * 8 + (lane & 7);     // s within block
    const int vcol2 = (wn * 16 + (lane >> 4) * 8) * 2;        // d offset bytes

    float oacc[4][2][4];
    float rs[4][2];
    #pragma unroll
    for (int mi = 0; mi < 4; mi++) {
        rs[mi][0] = rs[mi][1] = 0.f;
        #pragma unroll
        for (int p = 0; p < 2; p++)
            #pragma unroll
            for (int c = 0; c < 4; c++) oacc[mi][p][c] = 0.f;
    }

    for (int j = 0; j < TT / 128; j++) {
        const int k0 = j * 128;
        const uint32_t sVh = sVb + (j & 1) * 36864;
        const uint32_t sVl = sVh + 18432;
        CP_WAIT0();
        __syncthreads();

        // ---- S = Q K^T (3-term split); warp tile 64x32 ----
        float acc[4][4][4];
        #pragma unroll
        for (int mi = 0; mi < 4; mi++)
            #pragma unroll
            for (int nf = 0; nf < 4; nf++)
                #pragma unroll
                for (int c = 0; c < 4; c++) acc[mi][nf][c] = 0.f;

        #pragma unroll
        for (int ks = 0; ks < 4; ks++) {
            const int kc2 = ks * 32;
            uint32_t a[4][4], bh_[2][4], bl_[2][4];
            #pragma unroll
            for (int mi = 0; mi < 4; mi++)
                LDSM4(a[mi], sQh + (arow + mi * 16) * 144 + acol2 + kc2);
            #pragma unroll
            for (int p = 0; p < 2; p++)
                LDSM4(bh_[p], sKh + (brow + p * 16) * 144 + bcol2 + kc2);
            #pragma unroll
            for (int mi = 0; mi < 4; mi++)
                #pragma unroll
                for (int nf = 0; nf < 4; nf++)
                    MMA16816(acc[mi][nf], a[mi],
                             bh_[nf >> 1][(nf & 1) * 2], bh_[nf >> 1][(nf & 1) * 2 + 1]);
            #pragma unroll
            for (int p = 0; p < 2; p++)
                LDSM4(bl_[p], sKl + (brow + p * 16) * 144 + bcol2 + kc2);
            #pragma unroll
            for (int mi = 0; mi < 4; mi++)
                #pragma unroll
                for (int nf = 0; nf < 4; nf++)
                    MMA16816(acc[mi][nf], a[mi],
                             bl_[nf >> 1][(nf & 1) * 2], bl_[nf >> 1][(nf & 1) * 2 + 1]);
            #pragma unroll
            for (int mi = 0; mi < 4; mi++)
                LDSM4(a[mi], sQl + (arow + mi * 16) * 144 + acol2 + kc2);
            #pragma unroll
            for (int mi = 0; mi < 4; mi++)
                #pragma unroll
                for (int nf = 0; nf < 4; nf++)
                    MMA16816(acc[mi][nf], a[mi],
                             bh_[nf >> 1][(nf & 1) * 2], bh_[nf >> 1][(nf & 1) * 2 + 1]);
        }

        // ---- e = f * exp(S); row sums; store P hi/lo ----
        const int prow = wm * 64 + (lane >> 2);
        const int ncol = wn * 32 + 2 * (lane & 3);
        #pragma unroll
        for (int mi = 0; mi < 4; mi++) {
            #pragma unroll
            for (int nf = 0; nf < 4; nf++) {
                const int n = ncol + nf * 8;
                const int gq = q0 + prow + mi * 16;
                float2 f0 = *(const float2*)(fb + (size_t)gq * TT + k0 + n);
                float2 f1 = *(const float2*)(fb + (size_t)(gq + 8) * TT + k0 + n);
                float e00 = f0.x * __expf(acc[mi][nf][0]);
                float e01 = f0.y * __expf(acc[mi][nf][1]);
                float e10 = f1.x * __expf(acc[mi][nf][2]);
                float e11 = f1.y * __expf(acc[mi][nf][3]);
                rs[mi][0] += e00 + e01;
                rs[mi][1] += e10 + e11;
                __nv_bfloat16 h00, h01, h10, h11, l00, l01, l10, l11;
                split1(e00, h00, l00); split1(e01, h01, l01);
                split1(e10, h10, l10); split1(e11, h11, l11);
                const uint32_t off0 = (uint32_t)(prow + mi * 16) * 272 + n * 2;
                const uint32_t off1 = off0 + 8 * 272;
                *(__nv_bfloat162*)(sm + (sPh - S0) + off0) = __halves2bfloat162(h00, h01);
                *(__nv_bfloat162*)(sm + (sPl - S0) + off0) = __halves2bfloat162(l00, l01);
                *(__nv_bfloat162*)(sm + (sPh - S0) + off1) = __halves2bfloat162(h10, h11);
                *(__nv_bfloat162*)(sm + (sPl - S0) + off1) = __halves2bfloat162(l10, l11);
            }
        }
        __syncthreads();   // P visible; K fully consumed by all warps

        if (j + 1 < TT / 128) {
            const __nv_bfloat16* kh2 = kh + (size_t)(k0 + 128) * HD;
            const __nv_bfloat16* kl2 = kl + (size_t)(k0 + 128) * HD;
            const __nv_bfloat16* vh2 = vh + (size_t)(k0 + 128) * HD;
            const __nv_bfloat16* vl2 = vl + (size_t)(k0 + 128) * HD;
            const uint32_t sVn = sVb + ((j + 1) & 1) * 36864;
            load64(sKh, kh2);
            load64(sKl, kl2);
            load64(sVn, vh2);
            load64(sVn + 18432, vl2);
            CP_COMMIT();
        }

        // ---- O += P V (3-term split); warp tile 64x16 ----
        #pragma unroll
        for (int ks = 0; ks < 8; ks++) {
            uint32_t pa[4][4], vfh[4], vfl[4];
            #pragma unroll
            for (int mi = 0; mi < 4; mi++)
                LDSM4(pa[mi], sPh + (arow + mi * 16) * 272 + acol2 + ks * 32);
            LDSM4T(vfh, sVh + (ks * 16 + vrow0) * 144 + vcol2);
            #pragma unroll
            for (int mi = 0; mi < 4; mi++)
                #pragma unroll
                for (int p = 0; p < 2; p++)
                    MMA16816(oacc[mi][p], pa[mi], vfh[2 * p], vfh[2 * p + 1]);
            LDSM4T(vfl, sVl + (ks * 16 + vrow0) * 144 + vcol2);
            #pragma unroll
            for (int mi = 0; mi < 4; mi++)
                #pragma unroll
                for (int p = 0; p < 2; p++)
                    MMA16816(oacc[mi][p], pa[mi], vfl[2 * p], vfl[2 * p + 1]);
            #pragma unroll
            for (int mi = 0; mi < 4; mi++)
                LDSM4(pa[mi], sPl + (arow + mi * 16) * 272 + acol2 + ks * 32);
            #pragma unroll
            for (int mi = 0; mi < 4; mi++)
                #pragma unroll
                for (int p = 0; p < 2; p++)
                    MMA16816(oacc[mi][p], pa[mi], vfh[2 * p], vfh[2 * p + 1]);
        }
    }

    // ---- row-sum reduction and normalized output (bf16 hi/lo split) ----
    #pragma unroll
    for (int mi = 0; mi < 4; mi++)
        #pragma unroll
        for (int hf = 0; hf < 2; hf++) {
            float v = rs[mi][hf];
            v += __shfl_xor_sync(0xffffffffu, v, 1);
            v += __shfl_xor_sync(0xffffffffu, v, 2);
            rs[mi][hf] = v;
        }
    __syncthreads();
    if ((lane & 3) == 0) {
        #pragma unroll
        for (int mi = 0; mi < 4; mi++)
            #pragma unroll
            for (int hf = 0; hf < 2; hf++)
                rsum[wn * 128 + wm * 64 + mi * 16 + (lane >> 2) + hf * 8] = rs[mi][hf];
    }
    __syncthreads();

    const int dcol = h * 64 + wn * 16 + 2 * (lane & 3);
    #pragma unroll
    for (int mi = 0; mi < 4; mi++)
        #pragma unroll
        for (int hf = 0; hf < 2; hf++) {
            const int ml = wm * 64 + mi * 16 + (lane >> 2) + hf * 8;
            float tot = rsum[0 * 128 + ml] + rsum[1 * 128 + ml] +
                        rsum[2 * 128 + ml] + rsum[3 * 128 + ml];
            float inv = 1.0f / tot;
            size_t orow = (size_t)(b * TT + q0 + ml) * DD;
            #pragma unroll
            for (int p = 0; p < 2; p++) {
                float o0 = oacc[mi][p][hf * 2 + 0] * inv;
                float o1 = oacc[mi][p][hf * 2 + 1] * inv;
                __nv_bfloat16 h0, h1, l0, l1;
                split1(o0, h0, l0); split1(o1, h1, l1);
                *(__nv_bfloat162*)&g_aohi[orow + dcol + p * 8] = __halves2bfloat162(h0, h1);
                *(__nv_bfloat162*)&g_aolo[orow + dcol + p * 8] = __halves2bfloat162(l0, l1);
            }
        }
}

// ---------------------------------------------------------------------------
extern "C" void kernel_launch(void* const* d_in, const int* in_sizes, int n_in,
                              void* d_out, int out_size)
{
    const float* X  = (const float*)d_in[0];
    const float* F  = (const float*)d_in[1];
    const float* Wq = (const float*)d_in[2];
    const float* bq = (const float*)d_in[3];
    const float* Wk = (const float*)d_in[4];
    const float* bk = (const float*)d_in[5];
    const float* Wv = (const float*)d_in[6];
    const float* bv = (const float*)d_in[7];
    const float* Wo = (const float*)d_in[8];
    const float* bo = (const float*)d_in[9];
    float* out = (float*)d_out;

    __nv_bfloat16 *xhi, *xlo, *whi, *wlo;
    __nv_bfloat16 *qhi, *qlo, *khi, *klo, *vhi, *vlo, *aohi, *aolo;
    cudaGetSymbolAddress((void**)&xhi,  g_xhi);
    cudaGetSymbolAddress((void**)&xlo,  g_xlo);
    cudaGetSymbolAddress((void**)&whi,  g_whi);
    cudaGetSymbolAddress((void**)&wlo,  g_wlo);
    cudaGetSymbolAddress((void**)&qhi,  g_qhi);
    cudaGetSymbolAddress((void**)&qlo,  g_qlo);
    cudaGetSymbolAddress((void**)&khi,  g_khi);
    cudaGetSymbolAddress((void**)&klo,  g_klo);
    cudaGetSymbolAddress((void**)&vhi,  g_vhi);
    cudaGetSymbolAddress((void**)&vlo,  g_vlo);
    cudaGetSymbolAddress((void**)&aohi, g_aohi);
    cudaGetSymbolAddress((void**)&aolo, g_aolo);

    const int GEMM_SMEM = 2 * GSTAGE;   // 147456
    cudaFuncSetAttribute(gemm_mma,
                         cudaFuncAttributeMaxDynamicSharedMemorySize, GEMM_SMEM);
    cudaFuncSetAttribute(attn_mma,
                         cudaFuncAttributeMaxDynamicSharedMemorySize, AT_SMEM);

    const int NX4 = MM * KK / 4;
    const int NW4 = KK * KK / 4;
    split_bf16<<<NX4 / 256, 256>>>(X,  xhi, xlo, NX4);
    split_bf16<<<NW4 / 256, 256>>>(Wq, whi + 0*KK*KK, wlo + 0*KK*KK, NW4);
    split_bf16<<<NW4 / 256, 256>>>(Wk, whi + 1*KK*KK, wlo + 1*KK*KK, NW4);
    split_bf16<<<NW4 / 256, 256>>>(Wv, whi + 2*KK*KK, wlo + 2*KK*KK, NW4);
    split_bf16<<<NW4 / 256, 256>>>(Wo, whi + 3*KK*KK, wlo + 3*KK*KK, NW4);

    dim3 ggrid(DD / 128, MM / 128);   // (8, 32)
    gemm_mma<<<ggrid, 256, GEMM_SMEM>>>(xhi, xlo, whi + 0*KK*KK, wlo + 0*KK*KK,
                                        bq, nullptr, qhi, qlo, SCALING, 1);
    gemm_mma<<<ggrid, 256, GEMM_SMEM>>>(xhi, xlo, whi + 1*KK*KK, wlo + 1*KK*KK,
                                        bk, nullptr, khi, klo, 1.0f, 1);
    gemm_mma<<<ggrid, 256, GEMM_SMEM>>>(xhi, xlo, whi + 2*KK*KK, wlo + 2*KK*KK,
                                        bv, nullptr, vhi, vlo, 1.0f, 1);

    dim3 agrid(TT / 128, HH, BB);     // (16, 16, 2)
    attn_mma<<<agrid, 256, AT_SMEM>>>(F);

    gemm_mma<<<ggrid, 256, GEMM_SMEM>>>(aohi, aolo, whi + 3*KK*KK, wlo + 3*KK*KK,
                                        bo, out, nullptr, nullptr, 1.0f, 0);
}

// round 9
// speedup vs baseline: 2.5293x; 1.0152x over previous
#include <cuda_runtime.h>
#include <cuda_bf16.h>
#include <cstdint>

// Problem constants
#define BB   2
#define TT   2048
#define DD   1024
#define HH   16
#define HD   64
#define MM   (BB*TT)      // 4096
#define KK   1024
#define SCALING 0.125f    // 64^-0.5

// Scratch (device globals; no allocation allowed)
__device__ __nv_bfloat16 g_xhi[MM*KK],  g_xlo[MM*KK];
__device__ __nv_bfloat16 g_whi[4*KK*KK], g_wlo[4*KK*KK];
__device__ __nv_bfloat16 g_qhi[BB*HH*TT*HD], g_qlo[BB*HH*TT*HD];
__device__ __nv_bfloat16 g_khi[BB*HH*TT*HD], g_klo[BB*HH*TT*HD];
__device__ __nv_bfloat16 g_vhi[BB*HH*TT*HD], g_vlo[BB*HH*TT*HD];
__device__ __nv_bfloat16 g_aohi[MM*KK], g_aolo[MM*KK];

// ---------------------------------------------------------------------------
// Baseline-PTX helpers (valid at .target sm_103)
// ---------------------------------------------------------------------------
__device__ __forceinline__ uint32_t smem_u32(const void* p) {
    uint32_t a;
    asm("{ .reg .u64 t; cvta.to.shared.u64 t, %1; cvt.u32.u64 %0, t; }"
        : "=r"(a) : "l"(p));
    return a;
}

#define CP_ASYNC16(dst_u32, src_ptr) \
    asm volatile("cp.async.cg.shared.global [%0], [%1], 16;" \
                 :: "r"(dst_u32), "l"(src_ptr))
#define CP_COMMIT() asm volatile("cp.async.commit_group;" ::: "memory")
#define CP_WAIT1()  asm volatile("cp.async.wait_group 1;" ::: "memory")
#define CP_WAIT0()  asm volatile("cp.async.wait_group 0;" ::: "memory")

#define LDSM4(r, addr)                                                         \
    asm volatile("ldmatrix.sync.aligned.m8n8.x4.shared.b16 {%0,%1,%2,%3}, [%4];" \
        : "=r"((r)[0]), "=r"((r)[1]), "=r"((r)[2]), "=r"((r)[3]) : "r"(addr))

#define LDSM4T(r, addr)                                                        \
    asm volatile("ldmatrix.sync.aligned.m8n8.x4.trans.shared.b16 {%0,%1,%2,%3}, [%4];" \
        : "=r"((r)[0]), "=r"((r)[1]), "=r"((r)[2]), "=r"((r)[3]) : "r"(addr))

#define MMA16816(c, a, b0, b1)                                                 \
    asm volatile("mma.sync.aligned.m16n8k16.row.col.f32.bf16.bf16.f32 "        \
        "{%0,%1,%2,%3}, {%4,%5,%6,%7}, {%8,%9}, {%0,%1,%2,%3};"                \
        : "+f"((c)[0]), "+f"((c)[1]), "+f"((c)[2]), "+f"((c)[3])               \
        : "r"((a)[0]), "r"((a)[1]), "r"((a)[2]), "r"((a)[3]),                  \
          "r"(b0), "r"(b1))

__device__ __forceinline__ void split1(float x, __nv_bfloat16& h, __nv_bfloat16& l) {
    h = __float2bfloat16(x);
    l = __float2bfloat16(x - __bfloat162float(h));
}

// ---------------------------------------------------------------------------
// fp32 -> (bf16 hi, bf16 lo) splits
// ---------------------------------------------------------------------------
__device__ __forceinline__ void split_body(
    const float* __restrict__ in, __nv_bfloat16* __restrict__ hi,
    __nv_bfloat16* __restrict__ lo, int i)
{
    float4 v = ((const float4*)in)[i];
    __nv_bfloat16 h0, h1, h2, h3, l0, l1, l2, l3;
    split1(v.x, h0, l0); split1(v.y, h1, l1);
    split1(v.z, h2, l2); split1(v.w, h3, l3);
    ((__nv_bfloat162*)hi)[2*i]   = __halves2bfloat162(h0, h1);
    ((__nv_bfloat162*)hi)[2*i+1] = __halves2bfloat162(h2, h3);
    ((__nv_bfloat162*)lo)[2*i]   = __halves2bfloat162(l0, l1);
    ((__nv_bfloat162*)lo)[2*i+1] = __halves2bfloat162(l2, l3);
}

__global__ __launch_bounds__(256) void split_bf16(
    const float* __restrict__ in, __nv_bfloat16* __restrict__ hi,
    __nv_bfloat16* __restrict__ lo, int n4)
{
    int i = blockIdx.x * blockDim.x + threadIdx.x;
    if (i < n4) split_body(in, hi, lo, i);
}

// all 4 weight matrices in one launch (z picks the matrix)
__global__ __launch_bounds__(256) void split_w4(
    const float* __restrict__ W0, const float* __restrict__ W1,
    const float* __restrict__ W2, const float* __restrict__ W3,
    __nv_bfloat16* __restrict__ hi, __nv_bfloat16* __restrict__ lo)
{
    const int z = blockIdx.z;
    const float* in = (z == 0) ? W0 : (z == 1) ? W1 : (z == 2) ? W2 : W3;
    int i = blockIdx.x * blockDim.x + threadIdx.x;
    split_body(in, hi + (size_t)z * KK * KK, lo + (size_t)z * KK * KK, i);
}

// ---------------------------------------------------------------------------
// mma.sync GEMM core:  C[M,N] = (Ahi+Alo)[M,K] @ (Whi+Wlo)[N,K]^T + bias, *scale
// 128x128 tile per CTA, 8 warps 2(M)x4(N), warp tile 64x32.
// 3-stage cp.async pipeline, ONE __syncthreads per K-chunk of 64:
// chunk i+2 prefetch is issued before compute(i); stage reuse distance 3
// makes the post-compute barrier unnecessary.
// ---------------------------------------------------------------------------
#define CH 64
#define SKB 144
#define GTILE (128 * SKB)
#define GSTAGE (4 * GTILE)
#define NSTAGE 3
#define NCHUNK (KK / CH)

__device__ __forceinline__ void gemm_core(
    const __nv_bfloat16* __restrict__ Ahi, const __nv_bfloat16* __restrict__ Alo,
    const __nv_bfloat16* __restrict__ Whi, const __nv_bfloat16* __restrict__ Wlo,
    const float* __restrict__ bias, float* __restrict__ outF,
    __nv_bfloat16* __restrict__ outHi, __nv_bfloat16* __restrict__ outLo,
    float scale, int bhtd, char* sm, int m0, int n0)
{
    const int tid  = threadIdx.x;
    const int wid  = tid >> 5;
    const int lane = tid & 31;
    const int wm   = wid >> 2;
    const int wn   = wid & 3;

    const uint32_t sbase = smem_u32(sm);

    float acc[4][4][4];
    #pragma unroll
    for (int mi = 0; mi < 4; mi++)
        #pragma unroll
        for (int nf = 0; nf < 4; nf++)
            #pragma unroll
            for (int c = 0; c < 4; c++) acc[mi][nf][c] = 0.0f;

    auto load_chunk = [&](int k0, int stg) {
        uint32_t st = sbase + stg * GSTAGE;
        #pragma unroll
        for (int r = 0; r < 4; r++) {
            int e   = tid + r * 256;
            int row = e >> 3;
            int c   = e & 7;
            uint32_t d = st + row * SKB + c * 16;
            size_t ga = (size_t)(m0 + row) * KK + k0 + c * 8;
            size_t gw = (size_t)(n0 + row) * KK + k0 + c * 8;
            CP_ASYNC16(d + 0 * GTILE, (const char*)(Ahi + ga));
            CP_ASYNC16(d + 1 * GTILE, (const char*)(Alo + ga));
            CP_ASYNC16(d + 2 * GTILE, (const char*)(Whi + gw));
            CP_ASYNC16(d + 3 * GTILE, (const char*)(Wlo + gw));
        }
    };

    const int arow = wm * 64 + ((lane >> 3) & 1) * 8 + (lane & 7);
    const int acol = (lane >> 4) * 8;
    const int brow = wn * 32 + (lane >> 4) * 8 + (lane & 7);
    const int bcol = ((lane >> 3) & 1) * 8;

    auto compute_chunk = [&](int stg) {
        uint32_t st   = sbase + stg * GSTAGE;
        uint32_t aAhi = st + 0 * GTILE;
        uint32_t aAlo = st + 1 * GTILE;
        uint32_t aWhi = st + 2 * GTILE;
        uint32_t aWlo = st + 3 * GTILE;
        #pragma unroll
        for (int ks = 0; ks < 4; ks++) {
            const int kc2 = (ks * 16) * 2;
            uint32_t a[4][4], bh[2][4], bl[2][4];
            #pragma unroll
            for (int mi = 0; mi < 4; mi++)
                LDSM4(a[mi], aAhi + (arow + mi * 16) * SKB + (acol * 2 + kc2));
            #pragma unroll
            for (int p = 0; p < 2; p++)
                LDSM4(bh[p], aWhi + (brow + p * 16) * SKB + (bcol * 2 + kc2));
            #pragma unroll
            for (int mi = 0; mi < 4; mi++)
                #pragma unroll
                for (int nf = 0; nf < 4; nf++)
                    MMA16816(acc[mi][nf], a[mi],
                             bh[nf >> 1][(nf & 1) * 2], bh[nf >> 1][(nf & 1) * 2 + 1]);
            #pragma unroll
            for (int p = 0; p < 2; p++)
                LDSM4(bl[p], aWlo + (brow + p * 16) * SKB + (bcol * 2 + kc2));
            #pragma unroll
            for (int mi = 0; mi < 4; mi++)
                #pragma unroll
                for (int nf = 0; nf < 4; nf++)
                    MMA16816(acc[mi][nf], a[mi],
                             bl[nf >> 1][(nf & 1) * 2], bl[nf >> 1][(nf & 1) * 2 + 1]);
            #pragma unroll
            for (int mi = 0; mi < 4; mi++)
                LDSM4(a[mi], aAlo + (arow + mi * 16) * SKB + (acol * 2 + kc2));
            #pragma unroll
            for (int mi = 0; mi < 4; mi++)
                #pragma unroll
                for (int nf = 0; nf < 4; nf++)
                    MMA16816(acc[mi][nf], a[mi],
                             bh[nf >> 1][(nf & 1) * 2], bh[nf >> 1][(nf & 1) * 2 + 1]);
        }
    };

    load_chunk(0, 0);
    CP_COMMIT();
    load_chunk(CH, 1);
    CP_COMMIT();

    #pragma unroll 1
    for (int i = 0; i < NCHUNK; i++) {
        if (i < NCHUNK - 1) { CP_WAIT1(); } else { CP_WAIT0(); }
        __syncthreads();
        if (i + 2 < NCHUNK) {
            load_chunk((i + 2) * CH, (i + 2) % NSTAGE);
            CP_COMMIT();
        }
        compute_chunk(i % NSTAGE);
    }

    #pragma unroll
    for (int mi = 0; mi < 4; mi++) {
        #pragma unroll
        for (int nf = 0; nf < 4; nf++) {
            int r0 = m0 + wm * 64 + mi * 16 + (lane >> 2);
            int cc = n0 + wn * 32 + nf * 8 + 2 * (lane & 3);
            float b0 = bias[cc], b1 = bias[cc + 1];
            #pragma unroll
            for (int half = 0; half < 2; half++) {
                int r = r0 + half * 8;
                float vx = (acc[mi][nf][half * 2 + 0] + b0) * scale;
                float vy = (acc[mi][nf][half * 2 + 1] + b1) * scale;
                if (bhtd) {
                    int bbv = r >> 11, t = r & (TT - 1);
                    int hh = cc >> 6, d = cc & 63;
                    size_t idx = (((size_t)(bbv * HH + hh) * TT) + t) * HD + d;
                    __nv_bfloat16 h0, h1, l0, l1;
                    split1(vx, h0, l0); split1(vy, h1, l1);
                    *(__nv_bfloat162*)&outHi[idx] = __halves2bfloat162(h0, h1);
                    *(__nv_bfloat162*)&outLo[idx] = __halves2bfloat162(l0, l1);
                } else {
                    float2 v; v.x = vx; v.y = vy;
                    *(float2*)&outF[(size_t)r * DD + cc] = v;
                }
            }
        }
    }
}

// Fused Q/K/V projection: blockIdx.z in {0,1,2} selects weight/bias/output.
// 768 CTAs in one launch -> 5.19 waves instead of 3x2 = 6.
__global__ __launch_bounds__(256) void gemm_qkv(
    const __nv_bfloat16* __restrict__ Ahi, const __nv_bfloat16* __restrict__ Alo,
    const __nv_bfloat16* __restrict__ WhiAll, const __nv_bfloat16* __restrict__ WloAll,
    const float* __restrict__ bq, const float* __restrict__ bk,
    const float* __restrict__ bv,
    __nv_bfloat16* __restrict__ qhi, __nv_bfloat16* __restrict__ qlo,
    __nv_bfloat16* __restrict__ khi, __nv_bfloat16* __restrict__ klo,
    __nv_bfloat16* __restrict__ vhi, __nv_bfloat16* __restrict__ vlo)
{
    extern __shared__ char sm[];
    const int z = blockIdx.z;
    const __nv_bfloat16* Wh = WhiAll + (size_t)z * KK * KK;
    const __nv_bfloat16* Wl = WloAll + (size_t)z * KK * KK;
    const float* bias = (z == 0) ? bq : (z == 1) ? bk : bv;
    __nv_bfloat16* oh = (z == 0) ? qhi : (z == 1) ? khi : vhi;
    __nv_bfloat16* ol = (z == 0) ? qlo : (z == 1) ? klo : vlo;
    const float scale = (z == 0) ? SCALING : 1.0f;
    gemm_core(Ahi, Alo, Wh, Wl, bias, nullptr, oh, ol, scale, 1,
              sm, blockIdx.y * 128, blockIdx.x * 128);
}

// Output projection (fp32 row-major out)
__global__ __launch_bounds__(256) void gemm_wo(
    const __nv_bfloat16* __restrict__ Ahi, const __nv_bfloat16* __restrict__ Alo,
    const __nv_bfloat16* __restrict__ Whi, const __nv_bfloat16* __restrict__ Wlo,
    const float* __restrict__ bias, float* __restrict__ outF)
{
    extern __shared__ char sm[];
    gemm_core(Ahi, Alo, Whi, Wlo, bias, outF, nullptr, nullptr, 1.0f, 0,
              sm, blockIdx.y * 128, blockIdx.x * 128);
}

// ---------------------------------------------------------------------------
// Tensor-core fused attention (byte-identical to the R8 passing version).
// ---------------------------------------------------------------------------
#define AT_SMEM 219136

__global__ __launch_bounds__(256) void attn_mma(const float* __restrict__ F)
{
    extern __shared__ char sm[];
    const int tid = threadIdx.x, lane = tid & 31, wid = tid >> 5;
    const int wm = wid >> 2, wn = wid & 3;
    const int h = blockIdx.y, b = blockIdx.z;
    const int q0 = blockIdx.x * 128;

    const uint32_t S0 = smem_u32(sm);
    const uint32_t sQh = S0,          sQl = S0 + 18432;
    const uint32_t sKh = S0 + 36864,  sKl = S0 + 55296;
    const uint32_t sVb = S0 + 73728;
    const uint32_t sPh = S0 + 147456, sPl = S0 + 182272;
    float* rsum = (float*)(sm + 217088);

    const size_t hoff = ((size_t)(b * HH + h)) * TT * HD;
    const __nv_bfloat16 *qh = g_qhi + hoff, *ql = g_qlo + hoff;
    const __nv_bfloat16 *kh = g_khi + hoff, *kl = g_klo + hoff;
    const __nv_bfloat16 *vh = g_vhi + hoff, *vl = g_vlo + hoff;
    const float* fb = F + (size_t)b * TT * TT;

    auto load64 = [&](uint32_t dst, const __nv_bfloat16* src) {
        #pragma unroll
        for (int r = 0; r < 4; r++) {
            int e = tid + r * 256;
            int row = e >> 3, c = e & 7;
            CP_ASYNC16(dst + row * 144 + c * 16, src + (size_t)row * HD + c * 8);
        }
    };

    load64(sQh, qh + (size_t)q0 * HD);
    load64(sQl, ql + (size_t)q0 * HD);
    load64(sKh, kh);
    load64(sKl, kl);
    load64(sVb, vh);
    load64(sVb + 18432, vl);
    CP_COMMIT();

    const int arow  = wm * 64 + ((lane >> 3) & 1) * 8 + (lane & 7);
    const int acol2 = ((lane >> 4) * 8) * 2;
    const int brow  = wn * 32 + (lane >> 4) * 8 + (lane & 7);
    const int bcol2 = (((lane >> 3) & 1) * 8) * 2;
    const int vrow0 = ((lane >> 3) & 1) * 8 + (lane & 7);
    const int vcol2 = (wn * 16 + (lane >> 4) * 8) * 2;

    float oacc[4][2][4];
    float rs[4][2];
    #pragma unroll
    for (int mi = 0; mi < 4; mi++) {
        rs[mi][0] = rs[mi][1] = 0.f;
        #pragma unroll
        for (int p = 0; p < 2; p++)
            #pragma unroll
            for (int c = 0; c < 4; c++) oacc[mi][p][c] = 0.f;
    }

    for (int j = 0; j < TT / 128; j++) {
        const int k0 = j * 128;
        const uint32_t sVh = sVb + (j & 1) * 36864;
        const uint32_t sVl = sVh + 18432;
        CP_WAIT0();
        __syncthreads();

        float acc[4][4][4];
        #pragma unroll
        for (int mi = 0; mi < 4; mi++)
            #pragma unroll
            for (int nf = 0; nf < 4; nf++)
                #pragma unroll
                for (int c = 0; c < 4; c++) acc[mi][nf][c] = 0.f;

        #pragma unroll
        for (int ks = 0; ks < 4; ks++) {
            const int kc2 = ks * 32;
            uint32_t a[4][4], bh_[2][4], bl_[2][4];
            #pragma unroll
            for (int mi = 0; mi < 4; mi++)
                LDSM4(a[mi], sQh + (arow + mi * 16) * 144 + acol2 + kc2);
            #pragma unroll
            for (int p = 0; p < 2; p++)
                LDSM4(bh_[p], sKh + (brow + p * 16) * 144 + bcol2 + kc2);
            #pragma unroll
            for (int mi = 0; mi < 4; mi++)
                #pragma unroll
                for (int nf = 0; nf < 4; nf++)
                    MMA16816(acc[mi][nf], a[mi],
                             bh_[nf >> 1][(nf & 1) * 2], bh_[nf >> 1][(nf & 1) * 2 + 1]);
            #pragma unroll
            for (int p = 0; p < 2; p++)
                LDSM4(bl_[p], sKl + (brow + p * 16) * 144 + bcol2 + kc2);
            #pragma unroll
            for (int mi = 0; mi < 4; mi++)
                #pragma unroll
                for (int nf = 0; nf < 4; nf++)
                    MMA16816(acc[mi][nf], a[mi],
                             bl_[nf >> 1][(nf & 1) * 2], bl_[nf >> 1][(nf & 1) * 2 + 1]);
            #pragma unroll
            for (int mi = 0; mi < 4; mi++)
                LDSM4(a[mi], sQl + (arow + mi * 16) * 144 + acol2 + kc2);
            #pragma unroll
            for (int mi = 0; mi < 4; mi++)
                #pragma unroll
                for (int nf = 0; nf < 4; nf++)
                    MMA16816(acc[mi][nf], a[mi],
                             bh_[nf >> 1][(nf & 1) * 2], bh_[nf >> 1][(nf & 1) * 2 + 1]);
        }

        const int prow = wm * 64 + (lane >> 2);
        const int ncol = wn * 32 + 2 * (lane & 3);
        #pragma unroll
        for (int mi = 0; mi < 4; mi++) {
            #pragma unroll
            for (int nf = 0; nf < 4; nf++) {
                const int n = ncol + nf * 8;
                const int gq = q0 + prow + mi * 16;
                float2 f0 = *(const float2*)(fb + (size_t)gq * TT + k0 + n);
                float2 f1 = *(const float2*)(fb + (size_t)(gq + 8) * TT + k0 + n);
                float e00 = f0.x * __expf(acc[mi][nf][0]);
                float e01 = f0.y * __expf(acc[mi][nf][1]);
                float e10 = f1.x * __expf(acc[mi][nf][2]);
                float e11 = f1.y * __expf(acc[mi][nf][3]);
                rs[mi][0] += e00 + e01;
                rs[mi][1] += e10 + e11;
                __nv_bfloat16 h00, h01, h10, h11, l00, l01, l10, l11;
                split1(e00, h00, l00); split1(e01, h01, l01);
                split1(e10, h10, l10); split1(e11, h11, l11);
                const uint32_t off0 = (uint32_t)(prow + mi * 16) * 272 + n * 2;
                const uint32_t off1 = off0 + 8 * 272;
                *(__nv_bfloat162*)(sm + (sPh - S0) + off0) = __halves2bfloat162(h00, h01);
                *(__nv_bfloat162*)(sm + (sPl - S0) + off0) = __halves2bfloat162(l00, l01);
                *(__nv_bfloat162*)(sm + (sPh - S0) + off1) = __halves2bfloat162(h10, h11);
                *(__nv_bfloat162*)(sm + (sPl - S0) + off1) = __halves2bfloat162(l10, l11);
            }
        }
        __syncthreads();

        if (j + 1 < TT / 128) {
            const __nv_bfloat16* kh2 = kh + (size_t)(k0 + 128) * HD;
            const __nv_bfloat16* kl2 = kl + (size_t)(k0 + 128) * HD;
            const __nv_bfloat16* vh2 = vh + (size_t)(k0 + 128) * HD;
            const __nv_bfloat16* vl2 = vl + (size_t)(k0 + 128) * HD;
            const uint32_t sVn = sVb + ((j + 1) & 1) * 36864;
            load64(sKh, kh2);
            load64(sKl, kl2);
            load64(sVn, vh2);
            load64(sVn + 18432, vl2);
            CP_COMMIT();
        }

        #pragma unroll
        for (int ks = 0; ks < 8; ks++) {
            uint32_t pa[4][4], vfh[4], vfl[4];
            #pragma unroll
            for (int mi = 0; mi < 4; mi++)
                LDSM4(pa[mi], sPh + (arow + mi * 16) * 272 + acol2 + ks * 32);
            LDSM4T(vfh, sVh + (ks * 16 + vrow0) * 144 + vcol2);
            #pragma unroll
            for (int mi = 0; mi < 4; mi++)
                #pragma unroll
                for (int p = 0; p < 2; p++)
                    MMA16816(oacc[mi][p], pa[mi], vfh[2 * p], vfh[2 * p + 1]);
            LDSM4T(vfl, sVl + (ks * 16 + vrow0) * 144 + vcol2);
            #pragma unroll
            for (int mi = 0; mi < 4; mi++)
                #pragma unroll
                for (int p = 0; p < 2; p++)
                    MMA16816(oacc[mi][p], pa[mi], vfl[2 * p], vfl[2 * p + 1]);
            #pragma unroll
            for (int mi = 0; mi < 4; mi++)
                LDSM4(pa[mi], sPl + (arow + mi * 16) * 272 + acol2 + ks * 32);
            #pragma unroll
            for (int mi = 0; mi < 4; mi++)
                #pragma unroll
                for (int p = 0; p < 2; p++)
                    MMA16816(oacc[mi][p], pa[mi], vfh[2 * p], vfh[2 * p + 1]);
        }
    }

    #pragma unroll
    for (int mi = 0; mi < 4; mi++)
        #pragma unroll
        for (int hf = 0; hf < 2; hf++) {
            float v = rs[mi][hf];
            v += __shfl_xor_sync(0xffffffffu, v, 1);
            v += __shfl_xor_sync(0xffffffffu, v, 2);
            rs[mi][hf] = v;
        }
    __syncthreads();
    if ((lane & 3) == 0) {
        #pragma unroll
        for (int mi = 0; mi < 4; mi++)
            #pragma unroll
            for (int hf = 0; hf < 2; hf++)
                rsum[wn * 128 + wm * 64 + mi * 16 + (lane >> 2) + hf * 8] = rs[mi][hf];
    }
    __syncthreads();

    const int dcol = h * 64 + wn * 16 + 2 * (lane & 3);
    #pragma unroll
    for (int mi = 0; mi < 4; mi++)
        #pragma unroll
        for (int hf = 0; hf < 2; hf++) {
            const int ml = wm * 64 + mi * 16 + (lane >> 2) + hf * 8;
            float tot = rsum[0 * 128 + ml] + rsum[1 * 128 + ml] +
                        rsum[2 * 128 + ml] + rsum[3 * 128 + ml];
            float inv = 1.0f / tot;
            size_t orow = (size_t)(b * TT + q0 + ml) * DD;
            #pragma unroll
            for (int p = 0; p < 2; p++) {
                float o0 = oacc[mi][p][hf * 2 + 0] * inv;
                float o1 = oacc[mi][p][hf * 2 + 1] * inv;
                __nv_bfloat16 h0, h1, l0, l1;
                split1(o0, h0, l0); split1(o1, h1, l1);
                *(__nv_bfloat162*)&g_aohi[orow + dcol + p * 8] = __halves2bfloat162(h0, h1);
                *(__nv_bfloat162*)&g_aolo[orow + dcol + p * 8] = __halves2bfloat162(l0, l1);
            }
        }
}

// ---------------------------------------------------------------------------
extern "C" void kernel_launch(void* const* d_in, const int* in_sizes, int n_in,
                              void* d_out, int out_size)
{
    const float* X  = (const float*)d_in[0];
    const float* F  = (const float*)d_in[1];
    const float* Wq = (const float*)d_in[2];
    const float* bq = (const float*)d_in[3];
    const float* Wk = (const float*)d_in[4];
    const float* bk = (const float*)d_in[5];
    const float* Wv = (const float*)d_in[6];
    const float* bv = (const float*)d_in[7];
    const float* Wo = (const float*)d_in[8];
    const float* bo = (const float*)d_in[9];
    float* out = (float*)d_out;

    __nv_bfloat16 *xhi, *xlo, *whi, *wlo;
    __nv_bfloat16 *qhi, *qlo, *khi, *klo, *vhi, *vlo, *aohi, *aolo;
    cudaGetSymbolAddress((void**)&xhi,  g_xhi);
    cudaGetSymbolAddress((void**)&xlo,  g_xlo);
    cudaGetSymbolAddress((void**)&whi,  g_whi);
    cudaGetSymbolAddress((void**)&wlo,  g_wlo);
    cudaGetSymbolAddress((void**)&qhi,  g_qhi);
    cudaGetSymbolAddress((void**)&qlo,  g_qlo);
    cudaGetSymbolAddress((void**)&khi,  g_khi);
    cudaGetSymbolAddress((void**)&klo,  g_klo);
    cudaGetSymbolAddress((void**)&vhi,  g_vhi);
    cudaGetSymbolAddress((void**)&vlo,  g_vlo);
    cudaGetSymbolAddress((void**)&aohi, g_aohi);
    cudaGetSymbolAddress((void**)&aolo, g_aolo);

    const int GEMM_SMEM = NSTAGE * GSTAGE;   // 221184
    cudaFuncSetAttribute(gemm_qkv,
                         cudaFuncAttributeMaxDynamicSharedMemorySize, GEMM_SMEM);
    cudaFuncSetAttribute(gemm_wo,
                         cudaFuncAttributeMaxDynamicSharedMemorySize, GEMM_SMEM);
    cudaFuncSetAttribute(attn_mma,
                         cudaFuncAttributeMaxDynamicSharedMemorySize, AT_SMEM);

    const int NX4 = MM * KK / 4;
    const int NW4 = KK * KK / 4;
    split_bf16<<<NX4 / 256, 256>>>(X, xhi, xlo, NX4);
    dim3 wgrid(NW4 / 256, 1, 4);
    split_w4<<<wgrid, 256>>>(Wq, Wk, Wv, Wo, whi, wlo);

    dim3 qkvgrid(DD / 128, MM / 128, 3);   // (8, 32, 3) = 768 CTAs
    gemm_qkv<<<qkvgrid, 256, GEMM_SMEM>>>(xhi, xlo, whi, wlo, bq, bk, bv,
                                          qhi, qlo, khi, klo, vhi, vlo);

    dim3 agrid(TT / 128, HH, BB);          // (16, 16, 2)
    attn_mma<<<agrid, 256, AT_SMEM>>>(F);

    dim3 ogrid(DD / 128, MM / 128);        // (8, 32)
    gemm_wo<<<ogrid, 256, GEMM_SMEM>>>(aohi, aolo, whi + 3*(size_t)KK*KK,
                                       wlo + 3*(size_t)KK*KK, bo, out);
}

// round 13
// speedup vs baseline: 2.6744x; 1.0574x over previous
#include <cuda_runtime.h>
#include <cuda_bf16.h>
#include <cstdint>

// Problem constants
#define BB   2
#define TT   2048
#define DD   1024
#define HH   16
#define HD   64
#define MM   (BB*TT)      // 4096
#define KK   1024
#define SCALING 0.125f    // 64^-0.5

// Scratch (device globals; no allocation allowed)
__device__ __nv_bfloat16 g_xhi[MM*KK],  g_xlo[MM*KK];
__device__ __nv_bfloat16 g_whi[4*KK*KK], g_wlo[4*KK*KK];
__device__ __nv_bfloat16 g_qhi[BB*HH*TT*HD], g_qlo[BB*HH*TT*HD];
__device__ __nv_bfloat16 g_khi[BB*HH*TT*HD], g_klo[BB*HH*TT*HD];
__device__ __nv_bfloat16 g_vhi[BB*HH*TT*HD], g_vlo[BB*HH*TT*HD];
__device__ __nv_bfloat16 g_aohi[MM*KK], g_aolo[MM*KK];

// ---------------------------------------------------------------------------
// Baseline-PTX helpers (valid at .target sm_103)
// ---------------------------------------------------------------------------
__device__ __forceinline__ uint32_t smem_u32(const void* p) {
    uint32_t a;
    asm("{ .reg .u64 t; cvta.to.shared.u64 t, %1; cvt.u32.u64 %0, t; }"
        : "=r"(a) : "l"(p));
    return a;
}

#define CP_ASYNC16(dst_u32, src_ptr) \
    asm volatile("cp.async.cg.shared.global [%0], [%1], 16;" \
                 :: "r"(dst_u32), "l"(src_ptr))
#define CP_COMMIT() asm volatile("cp.async.commit_group;" ::: "memory")
#define CP_WAIT1()  asm volatile("cp.async.wait_group 1;" ::: "memory")
#define CP_WAIT0()  asm volatile("cp.async.wait_group 0;" ::: "memory")

#define LDSM4(r, addr)                                                         \
    asm volatile("ldmatrix.sync.aligned.m8n8.x4.shared.b16 {%0,%1,%2,%3}, [%4];" \
        : "=r"((r)[0]), "=r"((r)[1]), "=r"((r)[2]), "=r"((r)[3]) : "r"(addr))

#define LDSM4T(r, addr)                                                        \
    asm volatile("ldmatrix.sync.aligned.m8n8.x4.trans.shared.b16 {%0,%1,%2,%3}, [%4];" \
        : "=r"((r)[0]), "=r"((r)[1]), "=r"((r)[2]), "=r"((r)[3]) : "r"(addr))

#define MMA16816(c, a, b0, b1)                                                 \
    asm volatile("mma.sync.aligned.m16n8k16.row.col.f32.bf16.bf16.f32 "        \
        "{%0,%1,%2,%3}, {%4,%5,%6,%7}, {%8,%9}, {%0,%1,%2,%3};"                \
        : "+f"((c)[0]), "+f"((c)[1]), "+f"((c)[2]), "+f"((c)[3])               \
        : "r"((a)[0]), "r"((a)[1]), "r"((a)[2]), "r"((a)[3]),                  \
          "r"(b0), "r"(b1))

__device__ __forceinline__ void split1(float x, __nv_bfloat16& h, __nv_bfloat16& l) {
    h = __float2bfloat16(x);
    l = __float2bfloat16(x - __bfloat162float(h));
}

// ---------------------------------------------------------------------------
// fp32 -> (bf16 hi, bf16 lo) splits
// ---------------------------------------------------------------------------
__device__ __forceinline__ void split_body(
    const float* __restrict__ in, __nv_bfloat16* __restrict__ hi,
    __nv_bfloat16* __restrict__ lo, int i)
{
    float4 v = ((const float4*)in)[i];
    __nv_bfloat16 h0, h1, h2, h3, l0, l1, l2, l3;
    split1(v.x, h0, l0); split1(v.y, h1, l1);
    split1(v.z, h2, l2); split1(v.w, h3, l3);
    ((__nv_bfloat162*)hi)[2*i]   = __halves2bfloat162(h0, h1);
    ((__nv_bfloat162*)hi)[2*i+1] = __halves2bfloat162(h2, h3);
    ((__nv_bfloat162*)lo)[2*i]   = __halves2bfloat162(l0, l1);
    ((__nv_bfloat162*)lo)[2*i+1] = __halves2bfloat162(l2, l3);
}

__global__ __launch_bounds__(256) void split_bf16(
    const float* __restrict__ in, __nv_bfloat16* __restrict__ hi,
    __nv_bfloat16* __restrict__ lo, int n4)
{
    int i = blockIdx.x * blockDim.x + threadIdx.x;
    if (i < n4) split_body(in, hi, lo, i);
}

__global__ __launch_bounds__(256) void split_w4(
    const float* __restrict__ W0, const float* __restrict__ W1,
    const float* __restrict__ W2, const float* __restrict__ W3,
    __nv_bfloat16* __restrict__ hi, __nv_bfloat16* __restrict__ lo)
{
    const int z = blockIdx.z;
    const float* in = (z == 0) ? W0 : (z == 1) ? W1 : (z == 2) ? W2 : W3;
    int i = blockIdx.x * blockDim.x + threadIdx.x;
    split_body(in, hi + (size_t)z * KK * KK, lo + (size_t)z * KK * KK, i);
}

// ---------------------------------------------------------------------------
// mma.sync GEMM core (identical to R9 passing version)
// ---------------------------------------------------------------------------
#define CH 64
#define SKB 144
#define GTILE (128 * SKB)
#define GSTAGE (4 * GTILE)
#define NSTAGE 3
#define NCHUNK (KK / CH)

__device__ __forceinline__ void gemm_core(
    const __nv_bfloat16* __restrict__ Ahi, const __nv_bfloat16* __restrict__ Alo,
    const __nv_bfloat16* __restrict__ Whi, const __nv_bfloat16* __restrict__ Wlo,
    const float* __restrict__ bias, float* __restrict__ outF,
    __nv_bfloat16* __restrict__ outHi, __nv_bfloat16* __restrict__ outLo,
    float scale, int bhtd, char* sm, int m0, int n0)
{
    const int tid  = threadIdx.x;
    const int wid  = tid >> 5;
    const int lane = tid & 31;
    const int wm   = wid >> 2;
    const int wn   = wid & 3;

    const uint32_t sbase = smem_u32(sm);

    float acc[4][4][4];
    #pragma unroll
    for (int mi = 0; mi < 4; mi++)
        #pragma unroll
        for (int nf = 0; nf < 4; nf++)
            #pragma unroll
            for (int c = 0; c < 4; c++) acc[mi][nf][c] = 0.0f;

    auto load_chunk = [&](int k0, int stg) {
        uint32_t st = sbase + stg * GSTAGE;
        #pragma unroll
        for (int r = 0; r < 4; r++) {
            int e   = tid + r * 256;
            int row = e >> 3;
            int c   = e & 7;
            uint32_t d = st + row * SKB + c * 16;
            size_t ga = (size_t)(m0 + row) * KK + k0 + c * 8;
            size_t gw = (size_t)(n0 + row) * KK + k0 + c * 8;
            CP_ASYNC16(d + 0 * GTILE, (const char*)(Ahi + ga));
            CP_ASYNC16(d + 1 * GTILE, (const char*)(Alo + ga));
            CP_ASYNC16(d + 2 * GTILE, (const char*)(Whi + gw));
            CP_ASYNC16(d + 3 * GTILE, (const char*)(Wlo + gw));
        }
    };

    const int arow = wm * 64 + ((lane >> 3) & 1) * 8 + (lane & 7);
    const int acol = (lane >> 4) * 8;
    const int brow = wn * 32 + (lane >> 4) * 8 + (lane & 7);
    const int bcol = ((lane >> 3) & 1) * 8;

    auto compute_chunk = [&](int stg) {
        uint32_t st   = sbase + stg * GSTAGE;
        uint32_t aAhi = st + 0 * GTILE;
        uint32_t aAlo = st + 1 * GTILE;
        uint32_t aWhi = st + 2 * GTILE;
        uint32_t aWlo = st + 3 * GTILE;
        #pragma unroll
        for (int ks = 0; ks < 4; ks++) {
            const int kc2 = (ks * 16) * 2;
            uint32_t a[4][4], bh[2][4], bl[2][4];
            #pragma unroll
            for (int mi = 0; mi < 4; mi++)
                LDSM4(a[mi], aAhi + (arow + mi * 16) * SKB + (acol * 2 + kc2));
            #pragma unroll
            for (int p = 0; p < 2; p++)
                LDSM4(bh[p], aWhi + (brow + p * 16) * SKB + (bcol * 2 + kc2));
            #pragma unroll
            for (int mi = 0; mi < 4; mi++)
                #pragma unroll
                for (int nf = 0; nf < 4; nf++)
                    MMA16816(acc[mi][nf], a[mi],
                             bh[nf >> 1][(nf & 1) * 2], bh[nf >> 1][(nf & 1) * 2 + 1]);
            #pragma unroll
            for (int p = 0; p < 2; p++)
                LDSM4(bl[p], aWlo + (brow + p * 16) * SKB + (bcol * 2 + kc2));
            #pragma unroll
            for (int mi = 0; mi < 4; mi++)
                #pragma unroll
                for (int nf = 0; nf < 4; nf++)
                    MMA16816(acc[mi][nf], a[mi],
                             bl[nf >> 1][(nf & 1) * 2], bl[nf >> 1][(nf & 1) * 2 + 1]);
            #pragma unroll
            for (int mi = 0; mi < 4; mi++)
                LDSM4(a[mi], aAlo + (arow + mi * 16) * SKB + (acol * 2 + kc2));
            #pragma unroll
            for (int mi = 0; mi < 4; mi++)
                #pragma unroll
                for (int nf = 0; nf < 4; nf++)
                    MMA16816(acc[mi][nf], a[mi],
                             bh[nf >> 1][(nf & 1) * 2], bh[nf >> 1][(nf & 1) * 2 + 1]);
        }
    };

    load_chunk(0, 0);
    CP_COMMIT();
    load_chunk(CH, 1);
    CP_COMMIT();

    #pragma unroll 1
    for (int i = 0; i < NCHUNK; i++) {
        if (i < NCHUNK - 1) { CP_WAIT1(); } else { CP_WAIT0(); }
        __syncthreads();
        if (i + 2 < NCHUNK) {
            load_chunk((i + 2) * CH, (i + 2) % NSTAGE);
            CP_COMMIT();
        }
        compute_chunk(i % NSTAGE);
    }

    #pragma unroll
    for (int mi = 0; mi < 4; mi++) {
        #pragma unroll
        for (int nf = 0; nf < 4; nf++) {
            int r0 = m0 + wm * 64 + mi * 16 + (lane >> 2);
            int cc = n0 + wn * 32 + nf * 8 + 2 * (lane & 3);
            float b0 = bias[cc], b1 = bias[cc + 1];
            #pragma unroll
            for (int half = 0; half < 2; half++) {
                int r = r0 + half * 8;
                float vx = (acc[mi][nf][half * 2 + 0] + b0) * scale;
                float vy = (acc[mi][nf][half * 2 + 1] + b1) * scale;
                if (bhtd) {
                    int bbv = r >> 11, t = r & (TT - 1);
                    int hh = cc >> 6, d = cc & 63;
                    size_t idx = (((size_t)(bbv * HH + hh) * TT) + t) * HD + d;
                    __nv_bfloat16 h0, h1, l0, l1;
                    split1(vx, h0, l0); split1(vy, h1, l1);
                    *(__nv_bfloat162*)&outHi[idx] = __halves2bfloat162(h0, h1);
                    *(__nv_bfloat162*)&outLo[idx] = __halves2bfloat162(l0, l1);
                } else {
                    float2 v; v.x = vx; v.y = vy;
                    *(float2*)&outF[(size_t)r * DD + cc] = v;
                }
            }
        }
    }
}

__global__ __launch_bounds__(256) void gemm_qkv(
    const __nv_bfloat16* __restrict__ Ahi, const __nv_bfloat16* __restrict__ Alo,
    const __nv_bfloat16* __restrict__ WhiAll, const __nv_bfloat16* __restrict__ WloAll,
    const float* __restrict__ bq, const float* __restrict__ bk,
    const float* __restrict__ bv,
    __nv_bfloat16* __restrict__ qhi, __nv_bfloat16* __restrict__ qlo,
    __nv_bfloat16* __restrict__ khi, __nv_bfloat16* __restrict__ klo,
    __nv_bfloat16* __restrict__ vhi, __nv_bfloat16* __restrict__ vlo)
{
    extern __shared__ char sm[];
    const int z = blockIdx.z;
    const __nv_bfloat16* Wh = WhiAll + (size_t)z * KK * KK;
    const __nv_bfloat16* Wl = WloAll + (size_t)z * KK * KK;
    const float* bias = (z == 0) ? bq : (z == 1) ? bk : bv;
    __nv_bfloat16* oh = (z == 0) ? qhi : (z == 1) ? khi : vhi;
    __nv_bfloat16* ol = (z == 0) ? qlo : (z == 1) ? klo : vlo;
    const float scale = (z == 0) ? SCALING : 1.0f;
    gemm_core(Ahi, Alo, Wh, Wl, bias, nullptr, oh, ol, scale, 1,
              sm, blockIdx.y * 128, blockIdx.x * 128);
}

__global__ __launch_bounds__(256) void gemm_wo(
    const __nv_bfloat16* __restrict__ Ahi, const __nv_bfloat16* __restrict__ Alo,
    const __nv_bfloat16* __restrict__ Whi, const __nv_bfloat16* __restrict__ Wlo,
    const float* __restrict__ bias, float* __restrict__ outF)
{
    extern __shared__ char sm[];
    gemm_core(Ahi, Alo, Whi, Wlo, bias, outF, nullptr, nullptr, 1.0f, 0,
              sm, blockIdx.y * 128, blockIdx.x * 128);
}

// ---------------------------------------------------------------------------
// Tensor-core fused attention, v2: q-tile 64 x kv-tile 64, 128 threads
// (4 warps, 2Mx2N), smem 92.7KB -> 2 CTAs/SM. Two co-resident CTAs at
// independent phases keep the tensor pipe fed during exp/split phases.
// Same 3-term split math and fragment lane geometry as the passing R8/R9.
//
// smem layout (bytes): Qh 0, Ql 9216, Kh 18432, Kl 27648,
//   V stages: 36864 + stg*18432 (hi at +0, lo at +9216),
//   Ph 73728, Pl 82944, rsum 92160 (2*64 floats) -> total 92672
// ---------------------------------------------------------------------------
#define AT_SMEM 92672

__global__ __launch_bounds__(128, 2) void attn_mma(const float* __restrict__ F)
{
    extern __shared__ char sm[];
    const int tid = threadIdx.x, lane = tid & 31, wid = tid >> 5;
    const int wm = wid >> 1, wn = wid & 1;
    const int h = blockIdx.y, b = blockIdx.z;
    const int q0 = blockIdx.x * 64;

    const uint32_t S0 = smem_u32(sm);
    const uint32_t sQh = S0,          sQl = S0 + 9216;
    const uint32_t sKh = S0 + 18432,  sKl = S0 + 27648;
    const uint32_t sVb = S0 + 36864;              // + stg*18432; lo at +9216
    const uint32_t sPh = S0 + 73728,  sPl = S0 + 82944;
    float* rsum = (float*)(sm + 92160);           // [2][64]

    const size_t hoff = ((size_t)(b * HH + h)) * TT * HD;
    const __nv_bfloat16 *qh = g_qhi + hoff, *ql = g_qlo + hoff;
    const __nv_bfloat16 *kh = g_khi + hoff, *kl = g_klo + hoff;
    const __nv_bfloat16 *vh = g_vhi + hoff, *vl = g_vlo + hoff;
    const float* fb = F + (size_t)b * TT * TT;

    // one 64x64 bf16 tile (row stride 144B), 128 threads x 4 iters
    auto load64 = [&](uint32_t dst, const __nv_bfloat16* src) {
        #pragma unroll
        for (int r = 0; r < 4; r++) {
            int e = tid + r * 128;
            int row = e >> 3, c = e & 7;
            CP_ASYNC16(dst + row * 144 + c * 16, src + (size_t)row * HD + c * 8);
        }
    };

    load64(sQh, qh + (size_t)q0 * HD);
    load64(sQl, ql + (size_t)q0 * HD);
    load64(sKh, kh);
    load64(sKl, kl);
    load64(sVb, vh);
    load64(sVb + 9216, vl);
    CP_COMMIT();

    // fragment lane geometry (same per-lane math as verified R7/R8)
    const int arow  = wm * 32 + ((lane >> 3) & 1) * 8 + (lane & 7);
    const int acol2 = ((lane >> 4) * 8) * 2;
    const int brow  = wn * 32 + (lane >> 4) * 8 + (lane & 7);
    const int bcol2 = (((lane >> 3) & 1) * 8) * 2;
    const int vrow0 = ((lane >> 3) & 1) * 8 + (lane & 7);
    const int vcol2 = (wn * 32 + (lane >> 4) * 8) * 2;

    float oacc[2][4][4];
    float rs[2][2];
    #pragma unroll
    for (int mi = 0; mi < 2; mi++) {
        rs[mi][0] = rs[mi][1] = 0.f;
        #pragma unroll
        for (int p = 0; p < 4; p++)
            #pragma unroll
            for (int c = 0; c < 4; c++) oacc[mi][p][c] = 0.f;
    }

    #pragma unroll 1
    for (int j = 0; j < TT / 64; j++) {
        const int k0 = j * 64;
        const uint32_t sVh = sVb + (j & 1) * 18432;
        const uint32_t sVl = sVh + 9216;
        CP_WAIT0();
        __syncthreads();

        // ---- S = Q K^T (3-term split); warp tile 32x32 ----
        float acc[2][4][4];
        #pragma unroll
        for (int mi = 0; mi < 2; mi++)
            #pragma unroll
            for (int nf = 0; nf < 4; nf++)
                #pragma unroll
                for (int c = 0; c < 4; c++) acc[mi][nf][c] = 0.f;

        #pragma unroll
        for (int ks = 0; ks < 4; ks++) {
            const int kc2 = ks * 32;
            uint32_t a[2][4], bh_[2][4], bl_[2][4];
            #pragma unroll
            for (int mi = 0; mi < 2; mi++)
                LDSM4(a[mi], sQh + (arow + mi * 16) * 144 + acol2 + kc2);
            #pragma unroll
            for (int p = 0; p < 2; p++)
                LDSM4(bh_[p], sKh + (brow + p * 16) * 144 + bcol2 + kc2);
            #pragma unroll
            for (int mi = 0; mi < 2; mi++)
                #pragma unroll
                for (int nf = 0; nf < 4; nf++)
                    MMA16816(acc[mi][nf], a[mi],
                             bh_[nf >> 1][(nf & 1) * 2], bh_[nf >> 1][(nf & 1) * 2 + 1]);
            #pragma unroll
            for (int p = 0; p < 2; p++)
                LDSM4(bl_[p], sKl + (brow + p * 16) * 144 + bcol2 + kc2);
            #pragma unroll
            for (int mi = 0; mi < 2; mi++)
                #pragma unroll
                for (int nf = 0; nf < 4; nf++)
                    MMA16816(acc[mi][nf], a[mi],
                             bl_[nf >> 1][(nf & 1) * 2], bl_[nf >> 1][(nf & 1) * 2 + 1]);
            #pragma unroll
            for (int mi = 0; mi < 2; mi++)
                LDSM4(a[mi], sQl + (arow + mi * 16) * 144 + acol2 + kc2);
            #pragma unroll
            for (int mi = 0; mi < 2; mi++)
                #pragma unroll
                for (int nf = 0; nf < 4; nf++)
                    MMA16816(acc[mi][nf], a[mi],
                             bh_[nf >> 1][(nf & 1) * 2], bh_[nf >> 1][(nf & 1) * 2 + 1]);
        }

        // ---- e = f * exp(S); row sums; store P hi/lo ----
        const int prow = wm * 32 + (lane >> 2);
        const int ncol = wn * 32 + 2 * (lane & 3);
        #pragma unroll
        for (int mi = 0; mi < 2; mi++) {
            #pragma unroll
            for (int nf = 0; nf < 4; nf++) {
                const int n = ncol + nf * 8;
                const int gq = q0 + prow + mi * 16;
                float2 f0 = *(const float2*)(fb + (size_t)gq * TT + k0 + n);
                float2 f1 = *(const float2*)(fb + (size_t)(gq + 8) * TT + k0 + n);
                float e00 = f0.x * __expf(acc[mi][nf][0]);
                float e01 = f0.y * __expf(acc[mi][nf][1]);
                float e10 = f1.x * __expf(acc[mi][nf][2]);
                float e11 = f1.y * __expf(acc[mi][nf][3]);
                rs[mi][0] += e00 + e01;
                rs[mi][1] += e10 + e11;
                __nv_bfloat16 h00, h01, h10, h11, l00, l01, l10, l11;
                split1(e00, h00, l00); split1(e01, h01, l01);
                split1(e10, h10, l10); split1(e11, h11, l11);
                const uint32_t off0 = (uint32_t)(prow + mi * 16) * 144 + n * 2;
                const uint32_t off1 = off0 + 8 * 144;
                *(__nv_bfloat162*)(sm + (sPh - S0) + off0) = __halves2bfloat162(h00, h01);
                *(__nv_bfloat162*)(sm + (sPl - S0) + off0) = __halves2bfloat162(l00, l01);
                *(__nv_bfloat162*)(sm + (sPh - S0) + off1) = __halves2bfloat162(h10, h11);
                *(__nv_bfloat162*)(sm + (sPl - S0) + off1) = __halves2bfloat162(l10, l11);
            }
        }
        __syncthreads();   // P visible; K fully consumed by all warps

        if (j + 1 < TT / 64) {
            const uint32_t sVn = sVb + ((j + 1) & 1) * 18432;
            load64(sKh, kh + (size_t)(k0 + 64) * HD);
            load64(sKl, kl + (size_t)(k0 + 64) * HD);
            load64(sVn, vh + (size_t)(k0 + 64) * HD);
            load64(sVn + 9216, vl + (size_t)(k0 + 64) * HD);
            CP_COMMIT();
        }

        // ---- O += P V (3-term split); warp tile 32x32 ----
        #pragma unroll
        for (int ks = 0; ks < 4; ks++) {
            uint32_t pa[2][4], vfh[2][4], vfl[2][4];
            #pragma unroll
            for (int mi = 0; mi < 2; mi++)
                LDSM4(pa[mi], sPh + (arow + mi * 16) * 144 + acol2 + ks * 32);
            #pragma unroll
            for (int q = 0; q < 2; q++)
                LDSM4T(vfh[q], sVh + (ks * 16 + vrow0) * 144 + vcol2 + q * 32);
            #pragma unroll
            for (int mi = 0; mi < 2; mi++)
                #pragma unroll
                for (int p = 0; p < 4; p++)
                    MMA16816(oacc[mi][p], pa[mi],
                             vfh[p >> 1][(p & 1) * 2], vfh[p >> 1][(p & 1) * 2 + 1]);
            #pragma unroll
            for (int q = 0; q < 2; q++)
                LDSM4T(vfl[q], sVl + (ks * 16 + vrow0) * 144 + vcol2 + q * 32);
            #pragma unroll
            for (int mi = 0; mi < 2; mi++)
                #pragma unroll
                for (int p = 0; p < 4; p++)
                    MMA16816(oacc[mi][p], pa[mi],
                             vfl[p >> 1][(p & 1) * 2], vfl[p >> 1][(p & 1) * 2 + 1]);
            #pragma unroll
            for (int mi = 0; mi < 2; mi++)
                LDSM4(pa[mi], sPl + (arow + mi * 16) * 144 + acol2 + ks * 32);
            #pragma unroll
            for (int mi = 0; mi < 2; mi++)
                #pragma unroll
                for (int p = 0; p < 4; p++)
                    MMA16816(oacc[mi][p], pa[mi],
                             vfh[p >> 1][(p & 1) * 2], vfh[p >> 1][(p & 1) * 2 + 1]);
        }
    }

    // ---- row-sum reduction and normalized output (bf16 hi/lo split) ----
    #pragma unroll
    for (int mi = 0; mi < 2; mi++)
        #pragma unroll
        for (int hf = 0; hf < 2; hf++) {
            float v = rs[mi][hf];
            v += __shfl_xor_sync(0xffffffffu, v, 1);
            v += __shfl_xor_sync(0xffffffffu, v, 2);
            rs[mi][hf] = v;
        }
    __syncthreads();
    if ((lane & 3) == 0) {
        #pragma unroll
        for (int mi = 0; mi < 2; mi++)
            #pragma unroll
            for (int hf = 0; hf < 2; hf++)
                rsum[wn * 64 + wm * 32 + mi * 16 + (lane >> 2) + hf * 8] = rs[mi][hf];
    }
    __syncthreads();

    const int dcol = h * 64 + wn * 32 + 2 * (lane & 3);
    #pragma unroll
    for (int mi = 0; mi < 2; mi++)
        #pragma unroll
        for (int hf = 0; hf < 2; hf++) {
            const int ml = wm * 32 + mi * 16 + (lane >> 2) + hf * 8;
            float tot = rsum[ml] + rsum[64 + ml];
            float inv = 1.0f / tot;
            size_t orow = (size_t)(b * TT + q0 + ml) * DD;
            #pragma unroll
            for (int p = 0; p < 4; p++) {
                float o0 = oacc[mi][p][hf * 2 + 0] * inv;
                float o1 = oacc[mi][p][hf * 2 + 1] * inv;
                __nv_bfloat16 h0, h1, l0, l1;
                split1(o0, h0, l0); split1(o1, h1, l1);
                *(__nv_bfloat162*)&g_aohi[orow + dcol + p * 8] = __halves2bfloat162(h0, h1);
                *(__nv_bfloat162*)&g_aolo[orow + dcol + p * 8] = __halves2bfloat162(l0, l1);
            }
        }
}

// ---------------------------------------------------------------------------
extern "C" void kernel_launch(void* const* d_in, const int* in_sizes, int n_in,
                              void* d_out, int out_size)
{
    const float* X  = (const float*)d_in[0];
    const float* F  = (const float*)d_in[1];
    const float* Wq = (const float*)d_in[2];
    const float* bq = (const float*)d_in[3];
    const float* Wk = (const float*)d_in[4];
    const float* bk = (const float*)d_in[5];
    const float* Wv = (const float*)d_in[6];
    const float* bv = (const float*)d_in[7];
    const float* Wo = (const float*)d_in[8];
    const float* bo = (const float*)d_in[9];
    float* out = (float*)d_out;

    __nv_bfloat16 *xhi, *xlo, *whi, *wlo;
    __nv_bfloat16 *qhi, *qlo, *khi, *klo, *vhi, *vlo, *aohi, *aolo;
    cudaGetSymbolAddress((void**)&xhi,  g_xhi);
    cudaGetSymbolAddress((void**)&xlo,  g_xlo);
    cudaGetSymbolAddress((void**)&whi,  g_whi);
    cudaGetSymbolAddress((void**)&wlo,  g_wlo);
    cudaGetSymbolAddress((void**)&qhi,  g_qhi);
    cudaGetSymbolAddress((void**)&qlo,  g_qlo);
    cudaGetSymbolAddress((void**)&khi,  g_khi);
    cudaGetSymbolAddress((void**)&klo,  g_klo);
    cudaGetSymbolAddress((void**)&vhi,  g_vhi);
    cudaGetSymbolAddress((void**)&vlo,  g_vlo);
    cudaGetSymbolAddress((void**)&aohi, g_aohi);
    cudaGetSymbolAddress((void**)&aolo, g_aolo);

    const int GEMM_SMEM = NSTAGE * GSTAGE;   // 221184
    cudaFuncSetAttribute(gemm_qkv,
                         cudaFuncAttributeMaxDynamicSharedMemorySize, GEMM_SMEM);
    cudaFuncSetAttribute(gemm_wo,
                         cudaFuncAttributeMaxDynamicSharedMemorySize, GEMM_SMEM);
    cudaFuncSetAttribute(attn_mma,
                         cudaFuncAttributeMaxDynamicSharedMemorySize, AT_SMEM);

    const int NX4 = MM * KK / 4;
    const int NW4 = KK * KK / 4;
    split_bf16<<<NX4 / 256, 256>>>(X, xhi, xlo, NX4);
    dim3 wgrid(NW4 / 256, 1, 4);
    split_w4<<<wgrid, 256>>>(Wq, Wk, Wv, Wo, whi, wlo);

    dim3 qkvgrid(DD / 128, MM / 128, 3);   // 768 CTAs
    gemm_qkv<<<qkvgrid, 256, GEMM_SMEM>>>(xhi, xlo, whi, wlo, bq, bk, bv,
                                          qhi, qlo, khi, klo, vhi, vlo);

    dim3 agrid(TT / 64, HH, BB);           // (32, 16, 2) = 1024 CTAs
    attn_mma<<<agrid, 128, AT_SMEM>>>(F);

    dim3 ogrid(DD / 128, MM / 128);        // (8, 32)
    gemm_wo<<<ogrid, 256, GEMM_SMEM>>>(aohi, aolo, whi + 3*(size_t)KK*KK,
                                       wlo + 3*(size_t)KK*KK, bo, out);
}

// round 14
// speedup vs baseline: 2.7968x; 1.0458x over previous
#include <cuda_runtime.h>
#include <cuda_bf16.h>
#include <cstdint>

// Problem constants
#define BB   2
#define TT   2048
#define DD   1024
#define HH   16
#define HD   64
#define MM   (BB*TT)      // 4096
#define KK   1024
#define SCALING 0.125f    // 64^-0.5

// Scratch (device globals; no allocation allowed)
__device__ __nv_bfloat16 g_xhi[MM*KK],  g_xlo[MM*KK];
__device__ __nv_bfloat16 g_whi[4*KK*KK], g_wlo[4*KK*KK];
__device__ __nv_bfloat16 g_qhi[BB*HH*TT*HD], g_qlo[BB*HH*TT*HD];
__device__ __nv_bfloat16 g_khi[BB*HH*TT*HD], g_klo[BB*HH*TT*HD];
__device__ __nv_bfloat16 g_vhi[BB*HH*TT*HD], g_vlo[BB*HH*TT*HD];
__device__ __nv_bfloat16 g_aohi[MM*KK], g_aolo[MM*KK];

// ---------------------------------------------------------------------------
// Baseline-PTX helpers (valid at .target sm_103)
// ---------------------------------------------------------------------------
__device__ __forceinline__ uint32_t smem_u32(const void* p) {
    uint32_t a;
    asm("{ .reg .u64 t; cvta.to.shared.u64 t, %1; cvt.u32.u64 %0, t; }"
        : "=r"(a) : "l"(p));
    return a;
}

#define CP_ASYNC16(dst_u32, src_ptr) \
    asm volatile("cp.async.cg.shared.global [%0], [%1], 16;" \
                 :: "r"(dst_u32), "l"(src_ptr))
#define CP_COMMIT() asm volatile("cp.async.commit_group;" ::: "memory")
#define CP_WAIT1()  asm volatile("cp.async.wait_group 1;" ::: "memory")
#define CP_WAIT0()  asm volatile("cp.async.wait_group 0;" ::: "memory")

#define LDSM4(r, addr)                                                         \
    asm volatile("ldmatrix.sync.aligned.m8n8.x4.shared.b16 {%0,%1,%2,%3}, [%4];" \
        : "=r"((r)[0]), "=r"((r)[1]), "=r"((r)[2]), "=r"((r)[3]) : "r"(addr))

#define LDSM4T(r, addr)                                                        \
    asm volatile("ldmatrix.sync.aligned.m8n8.x4.trans.shared.b16 {%0,%1,%2,%3}, [%4];" \
        : "=r"((r)[0]), "=r"((r)[1]), "=r"((r)[2]), "=r"((r)[3]) : "r"(addr))

#define MMA16816(c, a, b0, b1)                                                 \
    asm volatile("mma.sync.aligned.m16n8k16.row.col.f32.bf16.bf16.f32 "        \
        "{%0,%1,%2,%3}, {%4,%5,%6,%7}, {%8,%9}, {%0,%1,%2,%3};"                \
        : "+f"((c)[0]), "+f"((c)[1]), "+f"((c)[2]), "+f"((c)[3])               \
        : "r"((a)[0]), "r"((a)[1]), "r"((a)[2]), "r"((a)[3]),                  \
          "r"(b0), "r"(b1))

__device__ __forceinline__ void split1(float x, __nv_bfloat16& h, __nv_bfloat16& l) {
    h = __float2bfloat16(x);
    l = __float2bfloat16(x - __bfloat162float(h));
}

// ---------------------------------------------------------------------------
// fp32 -> (bf16 hi, bf16 lo) splits
// ---------------------------------------------------------------------------
__device__ __forceinline__ void split_body(
    const float* __restrict__ in, __nv_bfloat16* __restrict__ hi,
    __nv_bfloat16* __restrict__ lo, int i)
{
    float4 v = ((const float4*)in)[i];
    __nv_bfloat16 h0, h1, h2, h3, l0, l1, l2, l3;
    split1(v.x, h0, l0); split1(v.y, h1, l1);
    split1(v.z, h2, l2); split1(v.w, h3, l3);
    ((__nv_bfloat162*)hi)[2*i]   = __halves2bfloat162(h0, h1);
    ((__nv_bfloat162*)hi)[2*i+1] = __halves2bfloat162(h2, h3);
    ((__nv_bfloat162*)lo)[2*i]   = __halves2bfloat162(l0, l1);
    ((__nv_bfloat162*)lo)[2*i+1] = __halves2bfloat162(l2, l3);
}

__global__ __launch_bounds__(256) void split_bf16(
    const float* __restrict__ in, __nv_bfloat16* __restrict__ hi,
    __nv_bfloat16* __restrict__ lo, int n4)
{
    int i = blockIdx.x * blockDim.x + threadIdx.x;
    if (i < n4) split_body(in, hi, lo, i);
}

__global__ __launch_bounds__(256) void split_w4(
    const float* __restrict__ W0, const float* __restrict__ W1,
    const float* __restrict__ W2, const float* __restrict__ W3,
    __nv_bfloat16* __restrict__ hi, __nv_bfloat16* __restrict__ lo)
{
    const int z = blockIdx.z;
    const float* in = (z == 0) ? W0 : (z == 1) ? W1 : (z == 2) ? W2 : W3;
    int i = blockIdx.x * blockDim.x + threadIdx.x;
    split_body(in, hi + (size_t)z * KK * KK, lo + (size_t)z * KK * KK, i);
}

// ---------------------------------------------------------------------------
// mma.sync GEMM core (identical to R9/R12 passing version)
// ---------------------------------------------------------------------------
#define CH 64
#define SKB 144
#define GTILE (128 * SKB)
#define GSTAGE (4 * GTILE)
#define NSTAGE 3
#define NCHUNK (KK / CH)

__device__ __forceinline__ void gemm_core(
    const __nv_bfloat16* __restrict__ Ahi, const __nv_bfloat16* __restrict__ Alo,
    const __nv_bfloat16* __restrict__ Whi, const __nv_bfloat16* __restrict__ Wlo,
    const float* __restrict__ bias, float* __restrict__ outF,
    __nv_bfloat16* __restrict__ outHi, __nv_bfloat16* __restrict__ outLo,
    float scale, int bhtd, char* sm, int m0, int n0)
{
    const int tid  = threadIdx.x;
    const int wid  = tid >> 5;
    const int lane = tid & 31;
    const int wm   = wid >> 2;
    const int wn   = wid & 3;

    const uint32_t sbase = smem_u32(sm);

    float acc[4][4][4];
    #pragma unroll
    for (int mi = 0; mi < 4; mi++)
        #pragma unroll
        for (int nf = 0; nf < 4; nf++)
            #pragma unroll
            for (int c = 0; c < 4; c++) acc[mi][nf][c] = 0.0f;

    auto load_chunk = [&](int k0, int stg) {
        uint32_t st = sbase + stg * GSTAGE;
        #pragma unroll
        for (int r = 0; r < 4; r++) {
            int e   = tid + r * 256;
            int row = e >> 3;
            int c   = e & 7;
            uint32_t d = st + row * SKB + c * 16;
            size_t ga = (size_t)(m0 + row) * KK + k0 + c * 8;
            size_t gw = (size_t)(n0 + row) * KK + k0 + c * 8;
            CP_ASYNC16(d + 0 * GTILE, (const char*)(Ahi + ga));
            CP_ASYNC16(d + 1 * GTILE, (const char*)(Alo + ga));
            CP_ASYNC16(d + 2 * GTILE, (const char*)(Whi + gw));
            CP_ASYNC16(d + 3 * GTILE, (const char*)(Wlo + gw));
        }
    };

    const int arow = wm * 64 + ((lane >> 3) & 1) * 8 + (lane & 7);
    const int acol = (lane >> 4) * 8;
    const int brow = wn * 32 + (lane >> 4) * 8 + (lane & 7);
    const int bcol = ((lane >> 3) & 1) * 8;

    auto compute_chunk = [&](int stg) {
        uint32_t st   = sbase + stg * GSTAGE;
        uint32_t aAhi = st + 0 * GTILE;
        uint32_t aAlo = st + 1 * GTILE;
        uint32_t aWhi = st + 2 * GTILE;
        uint32_t aWlo = st + 3 * GTILE;
        #pragma unroll
        for (int ks = 0; ks < 4; ks++) {
            const int kc2 = (ks * 16) * 2;
            uint32_t a[4][4], bh[2][4], bl[2][4];
            #pragma unroll
            for (int mi = 0; mi < 4; mi++)
                LDSM4(a[mi], aAhi + (arow + mi * 16) * SKB + (acol * 2 + kc2));
            #pragma unroll
            for (int p = 0; p < 2; p++)
                LDSM4(bh[p], aWhi + (brow + p * 16) * SKB + (bcol * 2 + kc2));
            #pragma unroll
            for (int mi = 0; mi < 4; mi++)
                #pragma unroll
                for (int nf = 0; nf < 4; nf++)
                    MMA16816(acc[mi][nf], a[mi],
                             bh[nf >> 1][(nf & 1) * 2], bh[nf >> 1][(nf & 1) * 2 + 1]);
            #pragma unroll
            for (int p = 0; p < 2; p++)
                LDSM4(bl[p], aWlo + (brow + p * 16) * SKB + (bcol * 2 + kc2));
            #pragma unroll
            for (int mi = 0; mi < 4; mi++)
                #pragma unroll
                for (int nf = 0; nf < 4; nf++)
                    MMA16816(acc[mi][nf], a[mi],
                             bl[nf >> 1][(nf & 1) * 2], bl[nf >> 1][(nf & 1) * 2 + 1]);
            #pragma unroll
            for (int mi = 0; mi < 4; mi++)
                LDSM4(a[mi], aAlo + (arow + mi * 16) * SKB + (acol * 2 + kc2));
            #pragma unroll
            for (int mi = 0; mi < 4; mi++)
                #pragma unroll
                for (int nf = 0; nf < 4; nf++)
                    MMA16816(acc[mi][nf], a[mi],
                             bh[nf >> 1][(nf & 1) * 2], bh[nf >> 1][(nf & 1) * 2 + 1]);
        }
    };

    load_chunk(0, 0);
    CP_COMMIT();
    load_chunk(CH, 1);
    CP_COMMIT();

    #pragma unroll 1
    for (int i = 0; i < NCHUNK; i++) {
        if (i < NCHUNK - 1) { CP_WAIT1(); } else { CP_WAIT0(); }
        __syncthreads();
        if (i + 2 < NCHUNK) {
            load_chunk((i + 2) * CH, (i + 2) % NSTAGE);
            CP_COMMIT();
        }
        compute_chunk(i % NSTAGE);
    }

    #pragma unroll
    for (int mi = 0; mi < 4; mi++) {
        #pragma unroll
        for (int nf = 0; nf < 4; nf++) {
            int r0 = m0 + wm * 64 + mi * 16 + (lane >> 2);
            int cc = n0 + wn * 32 + nf * 8 + 2 * (lane & 3);
            float b0 = bias[cc], b1 = bias[cc + 1];
            #pragma unroll
            for (int half = 0; half < 2; half++) {
                int r = r0 + half * 8;
                float vx = (acc[mi][nf][half * 2 + 0] + b0) * scale;
                float vy = (acc[mi][nf][half * 2 + 1] + b1) * scale;
                if (bhtd) {
                    int bbv = r >> 11, t = r & (TT - 1);
                    int hh = cc >> 6, d = cc & 63;
                    size_t idx = (((size_t)(bbv * HH + hh) * TT) + t) * HD + d;
                    __nv_bfloat16 h0, h1, l0, l1;
                    split1(vx, h0, l0); split1(vy, h1, l1);
                    *(__nv_bfloat162*)&outHi[idx] = __halves2bfloat162(h0, h1);
                    *(__nv_bfloat162*)&outLo[idx] = __halves2bfloat162(l0, l1);
                } else {
                    float2 v; v.x = vx; v.y = vy;
                    *(float2*)&outF[(size_t)r * DD + cc] = v;
                }
            }
        }
    }
}

__global__ __launch_bounds__(256) void gemm_qkv(
    const __nv_bfloat16* __restrict__ Ahi, const __nv_bfloat16* __restrict__ Alo,
    const __nv_bfloat16* __restrict__ WhiAll, const __nv_bfloat16* __restrict__ WloAll,
    const float* __restrict__ bq, const float* __restrict__ bk,
    const float* __restrict__ bv,
    __nv_bfloat16* __restrict__ qhi, __nv_bfloat16* __restrict__ qlo,
    __nv_bfloat16* __restrict__ khi, __nv_bfloat16* __restrict__ klo,
    __nv_bfloat16* __restrict__ vhi, __nv_bfloat16* __restrict__ vlo)
{
    extern __shared__ char sm[];
    const int z = blockIdx.z;
    const __nv_bfloat16* Wh = WhiAll + (size_t)z * KK * KK;
    const __nv_bfloat16* Wl = WloAll + (size_t)z * KK * KK;
    const float* bias = (z == 0) ? bq : (z == 1) ? bk : bv;
    __nv_bfloat16* oh = (z == 0) ? qhi : (z == 1) ? khi : vhi;
    __nv_bfloat16* ol = (z == 0) ? qlo : (z == 1) ? klo : vlo;
    const float scale = (z == 0) ? SCALING : 1.0f;
    gemm_core(Ahi, Alo, Wh, Wl, bias, nullptr, oh, ol, scale, 1,
              sm, blockIdx.y * 128, blockIdx.x * 128);
}

__global__ __launch_bounds__(256) void gemm_wo(
    const __nv_bfloat16* __restrict__ Ahi, const __nv_bfloat16* __restrict__ Alo,
    const __nv_bfloat16* __restrict__ Whi, const __nv_bfloat16* __restrict__ Wlo,
    const float* __restrict__ bias, float* __restrict__ outF)
{
    extern __shared__ char sm[];
    gemm_core(Ahi, Alo, Whi, Wlo, bias, outF, nullptr, nullptr, 1.0f, 0,
              sm, blockIdx.y * 128, blockIdx.x * 128);
}

// ---------------------------------------------------------------------------
// Tensor-core fused attention, v3: q-tile 64 x kv-tile 64, 128 threads,
// SINGLE-buffered V -> smem 74.2KB -> 3 CTAs/SM (12 warps/SM, 3/SMSP).
// Load schedule per kv tile j: [wait K(j),V(j)] QK -> exp/P-store -> sync ->
// issue K(j+1) -> PV -> sync -> issue V(j+1). The V-load serialization is
// absorbed by the two co-resident CTAs at other phases.
//
// smem (bytes): Qh 0, Ql 9216, Kh 18432, Kl 27648, Vh 36864, Vl 46080,
//               Ph 55296, Pl 64512, rsum 73728 -> total 74240
// ---------------------------------------------------------------------------
#define AT_SMEM 74240

__global__ __launch_bounds__(128, 3) void attn_mma(const float* __restrict__ F)
{
    extern __shared__ char sm[];
    const int tid = threadIdx.x, lane = tid & 31, wid = tid >> 5;
    const int wm = wid >> 1, wn = wid & 1;
    const int h = blockIdx.y, b = blockIdx.z;
    const int q0 = blockIdx.x * 64;

    const uint32_t S0 = smem_u32(sm);
    const uint32_t sQh = S0,          sQl = S0 + 9216;
    const uint32_t sKh = S0 + 18432,  sKl = S0 + 27648;
    const uint32_t sVh = S0 + 36864,  sVl = S0 + 46080;
    const uint32_t sPh = S0 + 55296,  sPl = S0 + 64512;
    float* rsum = (float*)(sm + 73728);           // [2][64]

    const size_t hoff = ((size_t)(b * HH + h)) * TT * HD;
    const __nv_bfloat16 *qh = g_qhi + hoff, *ql = g_qlo + hoff;
    const __nv_bfloat16 *kh = g_khi + hoff, *kl = g_klo + hoff;
    const __nv_bfloat16 *vh = g_vhi + hoff, *vl = g_vlo + hoff;
    const float* fb = F + (size_t)b * TT * TT;

    auto load64 = [&](uint32_t dst, const __nv_bfloat16* src) {
        #pragma unroll
        for (int r = 0; r < 4; r++) {
            int e = tid + r * 128;
            int row = e >> 3, c = e & 7;
            CP_ASYNC16(dst + row * 144 + c * 16, src + (size_t)row * HD + c * 8);
        }
    };

    load64(sQh, qh + (size_t)q0 * HD);
    load64(sQl, ql + (size_t)q0 * HD);
    load64(sKh, kh);
    load64(sKl, kl);
    load64(sVh, vh);
    load64(sVl, vl);
    CP_COMMIT();

    const int arow  = wm * 32 + ((lane >> 3) & 1) * 8 + (lane & 7);
    const int acol2 = ((lane >> 4) * 8) * 2;
    const int brow  = wn * 32 + (lane >> 4) * 8 + (lane & 7);
    const int bcol2 = (((lane >> 3) & 1) * 8) * 2;
    const int vrow0 = ((lane >> 3) & 1) * 8 + (lane & 7);
    const int vcol2 = (wn * 32 + (lane >> 4) * 8) * 2;

    float oacc[2][4][4];
    float rs[2][2];
    #pragma unroll
    for (int mi = 0; mi < 2; mi++) {
        rs[mi][0] = rs[mi][1] = 0.f;
        #pragma unroll
        for (int p = 0; p < 4; p++)
            #pragma unroll
            for (int c = 0; c < 4; c++) oacc[mi][p][c] = 0.f;
    }

    #pragma unroll 1
    for (int j = 0; j < TT / 64; j++) {
        const int k0 = j * 64;
        CP_WAIT0();            // K(j), V(j) (and Q on j=0) resident
        __syncthreads();

        // ---- S = Q K^T (3-term split); warp tile 32x32 ----
        float acc[2][4][4];
        #pragma unroll
        for (int mi = 0; mi < 2; mi++)
            #pragma unroll
            for (int nf = 0; nf < 4; nf++)
                #pragma unroll
                for (int c = 0; c < 4; c++) acc[mi][nf][c] = 0.f;

        #pragma unroll
        for (int ks = 0; ks < 4; ks++) {
            const int kc2 = ks * 32;
            uint32_t a[2][4], bh_[2][4], bl_[2][4];
            #pragma unroll
            for (int mi = 0; mi < 2; mi++)
                LDSM4(a[mi], sQh + (arow + mi * 16) * 144 + acol2 + kc2);
            #pragma unroll
            for (int p = 0; p < 2; p++)
                LDSM4(bh_[p], sKh + (brow + p * 16) * 144 + bcol2 + kc2);
            #pragma unroll
            for (int mi = 0; mi < 2; mi++)
                #pragma unroll
                for (int nf = 0; nf < 4; nf++)
                    MMA16816(acc[mi][nf], a[mi],
                             bh_[nf >> 1][(nf & 1) * 2], bh_[nf >> 1][(nf & 1) * 2 + 1]);
            #pragma unroll
            for (int p = 0; p < 2; p++)
                LDSM4(bl_[p], sKl + (brow + p * 16) * 144 + bcol2 + kc2);
            #pragma unroll
            for (int mi = 0; mi < 2; mi++)
                #pragma unroll
                for (int nf = 0; nf < 4; nf++)
                    MMA16816(acc[mi][nf], a[mi],
                             bl_[nf >> 1][(nf & 1) * 2], bl_[nf >> 1][(nf & 1) * 2 + 1]);
            #pragma unroll
            for (int mi = 0; mi < 2; mi++)
                LDSM4(a[mi], sQl + (arow + mi * 16) * 144 + acol2 + kc2);
            #pragma unroll
            for (int mi = 0; mi < 2; mi++)
                #pragma unroll
                for (int nf = 0; nf < 4; nf++)
                    MMA16816(acc[mi][nf], a[mi],
                             bh_[nf >> 1][(nf & 1) * 2], bh_[nf >> 1][(nf & 1) * 2 + 1]);
        }

        // ---- e = f * exp(S); row sums; store P hi/lo ----
        const int prow = wm * 32 + (lane >> 2);
        const int ncol = wn * 32 + 2 * (lane & 3);
        #pragma unroll
        for (int mi = 0; mi < 2; mi++) {
            #pragma unroll
            for (int nf = 0; nf < 4; nf++) {
                const int n = ncol + nf * 8;
                const int gq = q0 + prow + mi * 16;
                float2 f0 = *(const float2*)(fb + (size_t)gq * TT + k0 + n);
                float2 f1 = *(const float2*)(fb + (size_t)(gq + 8) * TT + k0 + n);
                float e00 = f0.x * __expf(acc[mi][nf][0]);
                float e01 = f0.y * __expf(acc[mi][nf][1]);
                float e10 = f1.x * __expf(acc[mi][nf][2]);
                float e11 = f1.y * __expf(acc[mi][nf][3]);
                rs[mi][0] += e00 + e01;
                rs[mi][1] += e10 + e11;
                __nv_bfloat16 h00, h01, h10, h11, l00, l01, l10, l11;
                split1(e00, h00, l00); split1(e01, h01, l01);
                split1(e10, h10, l10); split1(e11, h11, l11);
                const uint32_t off0 = (uint32_t)(prow + mi * 16) * 144 + n * 2;
                const uint32_t off1 = off0 + 8 * 144;
                *(__nv_bfloat162*)(sm + (sPh - S0) + off0) = __halves2bfloat162(h00, h01);
                *(__nv_bfloat162*)(sm + (sPl - S0) + off0) = __halves2bfloat162(l00, l01);
                *(__nv_bfloat162*)(sm + (sPh - S0) + off1) = __halves2bfloat162(h10, h11);
                *(__nv_bfloat162*)(sm + (sPl - S0) + off1) = __halves2bfloat162(l10, l11);
            }
        }
        __syncthreads();   // P visible; K fully consumed by all warps

        if (j + 1 < TT / 64) {            // K prefetch (K buffer now free)
            load64(sKh, kh + (size_t)(k0 + 64) * HD);
            load64(sKl, kl + (size_t)(k0 + 64) * HD);
            CP_COMMIT();
        }

        // ---- O += P V (3-term split); warp tile 32x32 ----
        #pragma unroll
        for (int ks = 0; ks < 4; ks++) {
            uint32_t pa[2][4], vfh[2][4], vfl[2][4];
            #pragma unroll
            for (int mi = 0; mi < 2; mi++)
                LDSM4(pa[mi], sPh + (arow + mi * 16) * 144 + acol2 + ks * 32);
            #pragma unroll
            for (int q = 0; q < 2; q++)
                LDSM4T(vfh[q], sVh + (ks * 16 + vrow0) * 144 + vcol2 + q * 32);
            #pragma unroll
            for (int mi = 0; mi < 2; mi++)
                #pragma unroll
                for (int p = 0; p < 4; p++)
                    MMA16816(oacc[mi][p], pa[mi],
                             vfh[p >> 1][(p & 1) * 2], vfh[p >> 1][(p & 1) * 2 + 1]);
            #pragma unroll
            for (int q = 0; q < 2; q++)
                LDSM4T(vfl[q], sVl + (ks * 16 + vrow0) * 144 + vcol2 + q * 32);
            #pragma unroll
            for (int mi = 0; mi < 2; mi++)
                #pragma unroll
                for (int p = 0; p < 4; p++)
                    MMA16816(oacc[mi][p], pa[mi],
                             vfl[p >> 1][(p & 1) * 2], vfl[p >> 1][(p & 1) * 2 + 1]);
            #pragma unroll
            for (int mi = 0; mi < 2; mi++)
                LDSM4(pa[mi], sPl + (arow + mi * 16) * 144 + acol2 + ks * 32);
            #pragma unroll
            for (int mi = 0; mi < 2; mi++)
                #pragma unroll
                for (int p = 0; p < 4; p++)
                    MMA16816(oacc[mi][p], pa[mi],
                             vfh[p >> 1][(p & 1) * 2], vfh[p >> 1][(p & 1) * 2 + 1]);
        }

        if (j + 1 < TT / 64) {
            __syncthreads();              // V fully consumed by all warps
            load64(sVh, vh + (size_t)(k0 + 64) * HD);
            load64(sVl, vl + (size_t)(k0 + 64) * HD);
            CP_COMMIT();
        }
    }

    // ---- row-sum reduction and normalized output (bf16 hi/lo split) ----
    #pragma unroll
    for (int mi = 0; mi < 2; mi++)
        #pragma unroll
        for (int hf = 0; hf < 2; hf++) {
            float v = rs[mi][hf];
            v += __shfl_xor_sync(0xffffffffu, v, 1);
            v += __shfl_xor_sync(0xffffffffu, v, 2);
            rs[mi][hf] = v;
        }
    __syncthreads();
    if ((lane & 3) == 0) {
        #pragma unroll
        for (int mi = 0; mi < 2; mi++)
            #pragma unroll
            for (int hf = 0; hf < 2; hf++)
                rsum[wn * 64 + wm * 32 + mi * 16 + (lane >> 2) + hf * 8] = rs[mi][hf];
    }
    __syncthreads();

    const int dcol = h * 64 + wn * 32 + 2 * (lane & 3);
    #pragma unroll
    for (int mi = 0; mi < 2; mi++)
        #pragma unroll
        for (int hf = 0; hf < 2; hf++) {
            const int ml = wm * 32 + mi * 16 + (lane >> 2) + hf * 8;
            float tot = rsum[ml] + rsum[64 + ml];
            float inv = 1.0f / tot;
            size_t orow = (size_t)(b * TT + q0 + ml) * DD;
            #pragma unroll
            for (int p = 0; p < 4; p++) {
                float o0 = oacc[mi][p][hf * 2 + 0] * inv;
                float o1 = oacc[mi][p][hf * 2 + 1] * inv;
                __nv_bfloat16 h0, h1, l0, l1;
                split1(o0, h0, l0); split1(o1, h1, l1);
                *(__nv_bfloat162*)&g_aohi[orow + dcol + p * 8] = __halves2bfloat162(h0, h1);
                *(__nv_bfloat162*)&g_aolo[orow + dcol + p * 8] = __halves2bfloat162(l0, l1);
            }
        }
}

// ---------------------------------------------------------------------------
extern "C" void kernel_launch(void* const* d_in, const int* in_sizes, int n_in,
                              void* d_out, int out_size)
{
    const float* X  = (const float*)d_in[0];
    const float* F  = (const float*)d_in[1];
    const float* Wq = (const float*)d_in[2];
    const float* bq = (const float*)d_in[3];
    const float* Wk = (const float*)d_in[4];
    const float* bk = (const float*)d_in[5];
    const float* Wv = (const float*)d_in[6];
    const float* bv = (const float*)d_in[7];
    const float* Wo = (const float*)d_in[8];
    const float* bo = (const float*)d_in[9];
    float* out = (float*)d_out;

    __nv_bfloat16 *xhi, *xlo, *whi, *wlo;
    __nv_bfloat16 *qhi, *qlo, *khi, *klo, *vhi, *vlo, *aohi, *aolo;
    cudaGetSymbolAddress((void**)&xhi,  g_xhi);
    cudaGetSymbolAddress((void**)&xlo,  g_xlo);
    cudaGetSymbolAddress((void**)&whi,  g_whi);
    cudaGetSymbolAddress((void**)&wlo,  g_wlo);
    cudaGetSymbolAddress((void**)&qhi,  g_qhi);
    cudaGetSymbolAddress((void**)&qlo,  g_qlo);
    cudaGetSymbolAddress((void**)&khi,  g_khi);
    cudaGetSymbolAddress((void**)&klo,  g_klo);
    cudaGetSymbolAddress((void**)&vhi,  g_vhi);
    cudaGetSymbolAddress((void**)&vlo,  g_vlo);
    cudaGetSymbolAddress((void**)&aohi, g_aohi);
    cudaGetSymbolAddress((void**)&aolo, g_aolo);

    const int GEMM_SMEM = NSTAGE * GSTAGE;   // 221184
    cudaFuncSetAttribute(gemm_qkv,
                         cudaFuncAttributeMaxDynamicSharedMemorySize, GEMM_SMEM);
    cudaFuncSetAttribute(gemm_wo,
                         cudaFuncAttributeMaxDynamicSharedMemorySize, GEMM_SMEM);
    cudaFuncSetAttribute(attn_mma,
                         cudaFuncAttributeMaxDynamicSharedMemorySize, AT_SMEM);

    const int NX4 = MM * KK / 4;
    const int NW4 = KK * KK / 4;
    split_bf16<<<NX4 / 256, 256>>>(X, xhi, xlo, NX4);
    dim3 wgrid(NW4 / 256, 1, 4);
    split_w4<<<wgrid, 256>>>(Wq, Wk, Wv, Wo, whi, wlo);

    dim3 qkvgrid(DD / 128, MM / 128, 3);   // 768 CTAs
    gemm_qkv<<<qkvgrid, 256, GEMM_SMEM>>>(xhi, xlo, whi, wlo, bq, bk, bv,
                                          qhi, qlo, khi, klo, vhi, vlo);

    dim3 agrid(TT / 64, HH, BB);           // (32, 16, 2) = 1024 CTAs
    attn_mma<<<agrid, 128, AT_SMEM>>>(F);

    dim3 ogrid(DD / 128, MM / 128);        // (8, 32)
    gemm_wo<<<ogrid, 256, GEMM_SMEM>>>(aohi, aolo, whi + 3*(size_t)KK*KK,
                                       wlo + 3*(size_t)KK*KK, bo, out);
}

// round 15
// speedup vs baseline: 3.2022x; 1.1449x over previous
#include <cuda_runtime.h>
#include <cuda_fp16.h>
#include <cstdint>

// Problem constants
#define BB   2
#define TT   2048
#define DD   1024
#define HH   16
#define HD   64
#define MM   (BB*TT)      // 4096
#define KK   1024
#define SCALING 0.125f    // 64^-0.5

// Scratch (device globals; no allocation allowed)  -- all fp16 now
__device__ __half g_xhi[MM*KK],  g_xlo[MM*KK];
__device__ __half g_whi[4*KK*KK], g_wlo[4*KK*KK];
__device__ __half g_qhi[BB*HH*TT*HD], g_qlo[BB*HH*TT*HD];
__device__ __half g_khi[BB*HH*TT*HD], g_klo[BB*HH*TT*HD];
__device__ __half g_vhi[BB*HH*TT*HD], g_vlo[BB*HH*TT*HD];
__device__ __half g_aohi[MM*KK], g_aolo[MM*KK];

// ---------------------------------------------------------------------------
// Baseline-PTX helpers (valid at .target sm_103)
// ---------------------------------------------------------------------------
__device__ __forceinline__ uint32_t smem_u32(const void* p) {
    uint32_t a;
    asm("{ .reg .u64 t; cvta.to.shared.u64 t, %1; cvt.u32.u64 %0, t; }"
        : "=r"(a) : "l"(p));
    return a;
}

#define CP_ASYNC16(dst_u32, src_ptr) \
    asm volatile("cp.async.cg.shared.global [%0], [%1], 16;" \
                 :: "r"(dst_u32), "l"(src_ptr))
#define CP_COMMIT() asm volatile("cp.async.commit_group;" ::: "memory")
#define CP_WAIT1()  asm volatile("cp.async.wait_group 1;" ::: "memory")
#define CP_WAIT0()  asm volatile("cp.async.wait_group 0;" ::: "memory")

#define LDSM4(r, addr)                                                         \
    asm volatile("ldmatrix.sync.aligned.m8n8.x4.shared.b16 {%0,%1,%2,%3}, [%4];" \
        : "=r"((r)[0]), "=r"((r)[1]), "=r"((r)[2]), "=r"((r)[3]) : "r"(addr))

#define LDSM4T(r, addr)                                                        \
    asm volatile("ldmatrix.sync.aligned.m8n8.x4.trans.shared.b16 {%0,%1,%2,%3}, [%4];" \
        : "=r"((r)[0]), "=r"((r)[1]), "=r"((r)[2]), "=r"((r)[3]) : "r"(addr))

// fp16 inputs, fp32 accumulate
#define MMA16816(c, a, b0, b1)                                                 \
    asm volatile("mma.sync.aligned.m16n8k16.row.col.f32.f16.f16.f32 "          \
        "{%0,%1,%2,%3}, {%4,%5,%6,%7}, {%8,%9}, {%0,%1,%2,%3};"                \
        : "+f"((c)[0]), "+f"((c)[1]), "+f"((c)[2]), "+f"((c)[3])               \
        : "r"((a)[0]), "r"((a)[1]), "r"((a)[2]), "r"((a)[3]),                  \
          "r"(b0), "r"(b1))

__device__ __forceinline__ void split1h(float x, __half& h, __half& l) {
    h = __float2half_rn(x);
    l = __float2half_rn(x - __half2float(h));
}

// ---------------------------------------------------------------------------
// fp32 -> (fp16 hi, fp16 lo) splits
// ---------------------------------------------------------------------------
__device__ __forceinline__ void split_body(
    const float* __restrict__ in, __half* __restrict__ hi,
    __half* __restrict__ lo, int i)
{
    float4 v = ((const float4*)in)[i];
    __half h0, h1, h2, h3, l0, l1, l2, l3;
    split1h(v.x, h0, l0); split1h(v.y, h1, l1);
    split1h(v.z, h2, l2); split1h(v.w, h3, l3);
    ((__half2*)hi)[2*i]   = __halves2half2(h0, h1);
    ((__half2*)hi)[2*i+1] = __halves2half2(h2, h3);
    ((__half2*)lo)[2*i]   = __halves2half2(l0, l1);
    ((__half2*)lo)[2*i+1] = __halves2half2(l2, l3);
}

__global__ __launch_bounds__(256) void split_fp16(
    const float* __restrict__ in, __half* __restrict__ hi,
    __half* __restrict__ lo, int n4)
{
    int i = blockIdx.x * blockDim.x + threadIdx.x;
    if (i < n4) split_body(in, hi, lo, i);
}

__global__ __launch_bounds__(256) void split_w4(
    const float* __restrict__ W0, const float* __restrict__ W1,
    const float* __restrict__ W2, const float* __restrict__ W3,
    __half* __restrict__ hi, __half* __restrict__ lo)
{
    const int z = blockIdx.z;
    const float* in = (z == 0) ? W0 : (z == 1) ? W1 : (z == 2) ? W2 : W3;
    int i = blockIdx.x * blockDim.x + threadIdx.x;
    split_body(in, hi + (size_t)z * KK * KK, lo + (size_t)z * KK * KK, i);
}

// ---------------------------------------------------------------------------
// mma.sync GEMM core (structure identical to R13; fp16 3-term split ->
// error ~2^-22, better than the old bf16 3-term)
// ---------------------------------------------------------------------------
#define CH 64
#define SKB 144
#define GTILE (128 * SKB)
#define GSTAGE (4 * GTILE)
#define NSTAGE 3
#define NCHUNK (KK / CH)

__device__ __forceinline__ void gemm_core(
    const __half* __restrict__ Ahi, const __half* __restrict__ Alo,
    const __half* __restrict__ Whi, const __half* __restrict__ Wlo,
    const float* __restrict__ bias, float* __restrict__ outF,
    __half* __restrict__ outHi, __half* __restrict__ outLo,
    float scale, int bhtd, char* sm, int m0, int n0)
{
    const int tid  = threadIdx.x;
    const int wid  = tid >> 5;
    const int lane = tid & 31;
    const int wm   = wid >> 2;
    const int wn   = wid & 3;

    const uint32_t sbase = smem_u32(sm);

    float acc[4][4][4];
    #pragma unroll
    for (int mi = 0; mi < 4; mi++)
        #pragma unroll
        for (int nf = 0; nf < 4; nf++)
            #pragma unroll
            for (int c = 0; c < 4; c++) acc[mi][nf][c] = 0.0f;

    auto load_chunk = [&](int k0, int stg) {
        uint32_t st = sbase + stg * GSTAGE;
        #pragma unroll
        for (int r = 0; r < 4; r++) {
            int e   = tid + r * 256;
            int row = e >> 3;
            int c   = e & 7;
            uint32_t d = st + row * SKB + c * 16;
            size_t ga = (size_t)(m0 + row) * KK + k0 + c * 8;
            size_t gw = (size_t)(n0 + row) * KK + k0 + c * 8;
            CP_ASYNC16(d + 0 * GTILE, (const char*)(Ahi + ga));
            CP_ASYNC16(d + 1 * GTILE, (const char*)(Alo + ga));
            CP_ASYNC16(d + 2 * GTILE, (const char*)(Whi + gw));
            CP_ASYNC16(d + 3 * GTILE, (const char*)(Wlo + gw));
        }
    };

    const int arow = wm * 64 + ((lane >> 3) & 1) * 8 + (lane & 7);
    const int acol = (lane >> 4) * 8;
    const int brow = wn * 32 + (lane >> 4) * 8 + (lane & 7);
    const int bcol = ((lane >> 3) & 1) * 8;

    auto compute_chunk = [&](int stg) {
        uint32_t st   = sbase + stg * GSTAGE;
        uint32_t aAhi = st + 0 * GTILE;
        uint32_t aAlo = st + 1 * GTILE;
        uint32_t aWhi = st + 2 * GTILE;
        uint32_t aWlo = st + 3 * GTILE;
        #pragma unroll
        for (int ks = 0; ks < 4; ks++) {
            const int kc2 = (ks * 16) * 2;
            uint32_t a[4][4], bh[2][4], bl[2][4];
            #pragma unroll
            for (int mi = 0; mi < 4; mi++)
                LDSM4(a[mi], aAhi + (arow + mi * 16) * SKB + (acol * 2 + kc2));
            #pragma unroll
            for (int p = 0; p < 2; p++)
                LDSM4(bh[p], aWhi + (brow + p * 16) * SKB + (bcol * 2 + kc2));
            #pragma unroll
            for (int mi = 0; mi < 4; mi++)
                #pragma unroll
                for (int nf = 0; nf < 4; nf++)
                    MMA16816(acc[mi][nf], a[mi],
                             bh[nf >> 1][(nf & 1) * 2], bh[nf >> 1][(nf & 1) * 2 + 1]);
            #pragma unroll
            for (int p = 0; p < 2; p++)
                LDSM4(bl[p], aWlo + (brow + p * 16) * SKB + (bcol * 2 + kc2));
            #pragma unroll
            for (int mi = 0; mi < 4; mi++)
                #pragma unroll
                for (int nf = 0; nf < 4; nf++)
                    MMA16816(acc[mi][nf], a[mi],
                             bl[nf >> 1][(nf & 1) * 2], bl[nf >> 1][(nf & 1) * 2 + 1]);
            #pragma unroll
            for (int mi = 0; mi < 4; mi++)
                LDSM4(a[mi], aAlo + (arow + mi * 16) * SKB + (acol * 2 + kc2));
            #pragma unroll
            for (int mi = 0; mi < 4; mi++)
                #pragma unroll
                for (int nf = 0; nf < 4; nf++)
                    MMA16816(acc[mi][nf], a[mi],
                             bh[nf >> 1][(nf & 1) * 2], bh[nf >> 1][(nf & 1) * 2 + 1]);
        }
    };

    load_chunk(0, 0);
    CP_COMMIT();
    load_chunk(CH, 1);
    CP_COMMIT();

    #pragma unroll 1
    for (int i = 0; i < NCHUNK; i++) {
        if (i < NCHUNK - 1) { CP_WAIT1(); } else { CP_WAIT0(); }
        __syncthreads();
        if (i + 2 < NCHUNK) {
            load_chunk((i + 2) * CH, (i + 2) % NSTAGE);
            CP_COMMIT();
        }
        compute_chunk(i % NSTAGE);
    }

    #pragma unroll
    for (int mi = 0; mi < 4; mi++) {
        #pragma unroll
        for (int nf = 0; nf < 4; nf++) {
            int r0 = m0 + wm * 64 + mi * 16 + (lane >> 2);
            int cc = n0 + wn * 32 + nf * 8 + 2 * (lane & 3);
            float b0 = bias[cc], b1 = bias[cc + 1];
            #pragma unroll
            for (int half = 0; half < 2; half++) {
                int r = r0 + half * 8;
                float vx = (acc[mi][nf][half * 2 + 0] + b0) * scale;
                float vy = (acc[mi][nf][half * 2 + 1] + b1) * scale;
                if (bhtd) {
                    int bbv = r >> 11, t = r & (TT - 1);
                    int hh = cc >> 6, d = cc & 63;
                    size_t idx = (((size_t)(bbv * HH + hh) * TT) + t) * HD + d;
                    __half h0, h1, l0, l1;
                    split1h(vx, h0, l0); split1h(vy, h1, l1);
                    *(__half2*)&outHi[idx] = __halves2half2(h0, h1);
                    *(__half2*)&outLo[idx] = __halves2half2(l0, l1);
                } else {
                    float2 v; v.x = vx; v.y = vy;
                    *(float2*)&outF[(size_t)r * DD + cc] = v;
                }
            }
        }
    }
}

__global__ __launch_bounds__(256) void gemm_qkv(
    const __half* __restrict__ Ahi, const __half* __restrict__ Alo,
    const __half* __restrict__ WhiAll, const __half* __restrict__ WloAll,
    const float* __restrict__ bq, const float* __restrict__ bk,
    const float* __restrict__ bv,
    __half* __restrict__ qhi, __half* __restrict__ qlo,
    __half* __restrict__ khi, __half* __restrict__ klo,
    __half* __restrict__ vhi, __half* __restrict__ vlo)
{
    extern __shared__ char sm[];
    const int z = blockIdx.z;
    const __half* Wh = WhiAll + (size_t)z * KK * KK;
    const __half* Wl = WloAll + (size_t)z * KK * KK;
    const float* bias = (z == 0) ? bq : (z == 1) ? bk : bv;
    __half* oh = (z == 0) ? qhi : (z == 1) ? khi : vhi;
    __half* ol = (z == 0) ? qlo : (z == 1) ? klo : vlo;
    const float scale = (z == 0) ? SCALING : 1.0f;
    gemm_core(Ahi, Alo, Wh, Wl, bias, nullptr, oh, ol, scale, 1,
              sm, blockIdx.y * 128, blockIdx.x * 128);
}

__global__ __launch_bounds__(256) void gemm_wo(
    const __half* __restrict__ Ahi, const __half* __restrict__ Alo,
    const __half* __restrict__ Whi, const __half* __restrict__ Wlo,
    const float* __restrict__ bias, float* __restrict__ outF)
{
    extern __shared__ char sm[];
    gemm_core(Ahi, Alo, Whi, Wlo, bias, outF, nullptr, nullptr, 1.0f, 0,
              sm, blockIdx.y * 128, blockIdx.x * 128);
}

// ---------------------------------------------------------------------------
// Tensor-core fused attention, v4 (fp16 precision re-budget):
//  - QK^T: SINGLE fp16 term (S abs err ~1.6e-4; |S|~0.4 so e^S rel err ~1.6e-4)
//  - P: single fp16 in smem (rel err 2.8e-4)
//  - PV: P x (Vhi + Vlo), 2 terms (V split exact to 2^-22)
// Same 64x64 tiling / 128 thr / 3 CTAs/SM / K-then-V prefetch as R13.
//
// smem (bytes): Q 0, K 9216, Vh 18432, Vl 27648, P 36864, rsum 46080
//               -> total 46592
// ---------------------------------------------------------------------------
#define AT_SMEM 46592

__global__ __launch_bounds__(128, 3) void attn_mma(const float* __restrict__ F)
{
    extern __shared__ char sm[];
    const int tid = threadIdx.x, lane = tid & 31, wid = tid >> 5;
    const int wm = wid >> 1, wn = wid & 1;
    const int h = blockIdx.y, b = blockIdx.z;
    const int q0 = blockIdx.x * 64;

    const uint32_t S0 = smem_u32(sm);
    const uint32_t sQ  = S0;
    const uint32_t sK  = S0 + 9216;
    const uint32_t sVh = S0 + 18432, sVl = S0 + 27648;
    const uint32_t sP  = S0 + 36864;
    float* rsum = (float*)(sm + 46080);           // [2][64]

    const size_t hoff = ((size_t)(b * HH + h)) * TT * HD;
    const __half *qh = g_qhi + hoff;
    const __half *kh = g_khi + hoff;
    const __half *vh = g_vhi + hoff, *vl = g_vlo + hoff;
    const float* fb = F + (size_t)b * TT * TT;

    auto load64 = [&](uint32_t dst, const __half* src) {
        #pragma unroll
        for (int r = 0; r < 4; r++) {
            int e = tid + r * 128;
            int row = e >> 3, c = e & 7;
            CP_ASYNC16(dst + row * 144 + c * 16, src + (size_t)row * HD + c * 8);
        }
    };

    load64(sQ,  qh + (size_t)q0 * HD);
    load64(sK,  kh);
    load64(sVh, vh);
    load64(sVl, vl);
    CP_COMMIT();

    const int arow  = wm * 32 + ((lane >> 3) & 1) * 8 + (lane & 7);
    const int acol2 = ((lane >> 4) * 8) * 2;
    const int brow  = wn * 32 + (lane >> 4) * 8 + (lane & 7);
    const int bcol2 = (((lane >> 3) & 1) * 8) * 2;
    const int vrow0 = ((lane >> 3) & 1) * 8 + (lane & 7);
    const int vcol2 = (wn * 32 + (lane >> 4) * 8) * 2;

    float oacc[2][4][4];
    float rs[2][2];
    #pragma unroll
    for (int mi = 0; mi < 2; mi++) {
        rs[mi][0] = rs[mi][1] = 0.f;
        #pragma unroll
        for (int p = 0; p < 4; p++)
            #pragma unroll
            for (int c = 0; c < 4; c++) oacc[mi][p][c] = 0.f;
    }

    #pragma unroll 1
    for (int j = 0; j < TT / 64; j++) {
        const int k0 = j * 64;
        CP_WAIT0();            // K(j), V(j) (and Q on j=0) resident
        __syncthreads();

        // ---- S = Q K^T (single fp16 term); warp tile 32x32 ----
        float acc[2][4][4];
        #pragma unroll
        for (int mi = 0; mi < 2; mi++)
            #pragma unroll
            for (int nf = 0; nf < 4; nf++)
                #pragma unroll
                for (int c = 0; c < 4; c++) acc[mi][nf][c] = 0.f;

        #pragma unroll
        for (int ks = 0; ks < 4; ks++) {
            const int kc2 = ks * 32;
            uint32_t a[2][4], b_[2][4];
            #pragma unroll
            for (int mi = 0; mi < 2; mi++)
                LDSM4(a[mi], sQ + (arow + mi * 16) * 144 + acol2 + kc2);
            #pragma unroll
            for (int p = 0; p < 2; p++)
                LDSM4(b_[p], sK + (brow + p * 16) * 144 + bcol2 + kc2);
            #pragma unroll
            for (int mi = 0; mi < 2; mi++)
                #pragma unroll
                for (int nf = 0; nf < 4; nf++)
                    MMA16816(acc[mi][nf], a[mi],
                             b_[nf >> 1][(nf & 1) * 2], b_[nf >> 1][(nf & 1) * 2 + 1]);
        }

        // ---- e = f * exp(S); row sums; store P (single fp16) ----
        const int prow = wm * 32 + (lane >> 2);
        const int ncol = wn * 32 + 2 * (lane & 3);
        #pragma unroll
        for (int mi = 0; mi < 2; mi++) {
            #pragma unroll
            for (int nf = 0; nf < 4; nf++) {
                const int n = ncol + nf * 8;
                const int gq = q0 + prow + mi * 16;
                float2 f0 = *(const float2*)(fb + (size_t)gq * TT + k0 + n);
                float2 f1 = *(const float2*)(fb + (size_t)(gq + 8) * TT + k0 + n);
                float e00 = f0.x * __expf(acc[mi][nf][0]);
                float e01 = f0.y * __expf(acc[mi][nf][1]);
                float e10 = f1.x * __expf(acc[mi][nf][2]);
                float e11 = f1.y * __expf(acc[mi][nf][3]);
                rs[mi][0] += e00 + e01;
                rs[mi][1] += e10 + e11;
                const uint32_t off0 = (uint32_t)(prow + mi * 16) * 144 + n * 2;
                const uint32_t off1 = off0 + 8 * 144;
                *(__half2*)(sm + (sP - S0) + off0) =
                    __halves2half2(__float2half_rn(e00), __float2half_rn(e01));
                *(__half2*)(sm + (sP - S0) + off1) =
                    __halves2half2(__float2half_rn(e10), __float2half_rn(e11));
            }
        }
        __syncthreads();   // P visible; K fully consumed by all warps

        if (j + 1 < TT / 64) {            // K prefetch (K buffer now free)
            load64(sK, kh + (size_t)(k0 + 64) * HD);
            CP_COMMIT();
        }

        // ---- O += P (Vhi + Vlo); warp tile 32x32 ----
        #pragma unroll
        for (int ks = 0; ks < 4; ks++) {
            uint32_t pa[2][4], vfh[2][4], vfl[2][4];
            #pragma unroll
            for (int mi = 0; mi < 2; mi++)
                LDSM4(pa[mi], sP + (arow + mi * 16) * 144 + acol2 + ks * 32);
            #pragma unroll
            for (int q = 0; q < 2; q++)
                LDSM4T(vfh[q], sVh + (ks * 16 + vrow0) * 144 + vcol2 + q * 32);
            #pragma unroll
            for (int mi = 0; mi < 2; mi++)
                #pragma unroll
                for (int p = 0; p < 4; p++)
                    MMA16816(oacc[mi][p], pa[mi],
                             vfh[p >> 1][(p & 1) * 2], vfh[p >> 1][(p & 1) * 2 + 1]);
            #pragma unroll
            for (int q = 0; q < 2; q++)
                LDSM4T(vfl[q], sVl + (ks * 16 + vrow0) * 144 + vcol2 + q * 32);
            #pragma unroll
            for (int mi = 0; mi < 2; mi++)
                #pragma unroll
                for (int p = 0; p < 4; p++)
                    MMA16816(oacc[mi][p], pa[mi],
                             vfl[p >> 1][(p & 1) * 2], vfl[p >> 1][(p & 1) * 2 + 1]);
        }

        if (j + 1 < TT / 64) {
            __syncthreads();              // V fully consumed by all warps
            load64(sVh, vh + (size_t)(k0 + 64) * HD);
            load64(sVl, vl + (size_t)(k0 + 64) * HD);
            CP_COMMIT();
        }
    }

    // ---- row-sum reduction and normalized output (fp16 hi/lo split) ----
    #pragma unroll
    for (int mi = 0; mi < 2; mi++)
        #pragma unroll
        for (int hf = 0; hf < 2; hf++) {
            float v = rs[mi][hf];
            v += __shfl_xor_sync(0xffffffffu, v, 1);
            v += __shfl_xor_sync(0xffffffffu, v, 2);
            rs[mi][hf] = v;
        }
    __syncthreads();
    if ((lane & 3) == 0) {
        #pragma unroll
        for (int mi = 0; mi < 2; mi++)
            #pragma unroll
            for (int hf = 0; hf < 2; hf++)
                rsum[wn * 64 + wm * 32 + mi * 16 + (lane >> 2) + hf * 8] = rs[mi][hf];
    }
    __syncthreads();

    const int dcol = h * 64 + wn * 32 + 2 * (lane & 3);
    #pragma unroll
    for (int mi = 0; mi < 2; mi++)
        #pragma unroll
        for (int hf = 0; hf < 2; hf++) {
            const int ml = wm * 32 + mi * 16 + (lane >> 2) + hf * 8;
            float tot = rsum[ml] + rsum[64 + ml];
            float inv = 1.0f / tot;
            size_t orow = (size_t)(b * TT + q0 + ml) * DD;
            #pragma unroll
            for (int p = 0; p < 4; p++) {
                float o0 = oacc[mi][p][hf * 2 + 0] * inv;
                float o1 = oacc[mi][p][hf * 2 + 1] * inv;
                __half h0, h1, l0, l1;
                split1h(o0, h0, l0); split1h(o1, h1, l1);
                *(__half2*)&g_aohi[orow + dcol + p * 8] = __halves2half2(h0, h1);
                *(__half2*)&g_aolo[orow + dcol + p * 8] = __halves2half2(l0, l1);
            }
        }
}

// ---------------------------------------------------------------------------
extern "C" void kernel_launch(void* const* d_in, const int* in_sizes, int n_in,
                              void* d_out, int out_size)
{
    const float* X  = (const float*)d_in[0];
    const float* F  = (const float*)d_in[1];
    const float* Wq = (const float*)d_in[2];
    const float* bq = (const float*)d_in[3];
    const float* Wk = (const float*)d_in[4];
    const float* bk = (const float*)d_in[5];
    const float* Wv = (const float*)d_in[6];
    const float* bv = (const float*)d_in[7];
    const float* Wo = (const float*)d_in[8];
    const float* bo = (const float*)d_in[9];
    float* out = (float*)d_out;

    __half *xhi, *xlo, *whi, *wlo;
    __half *qhi, *qlo, *khi, *klo, *vhi, *vlo, *aohi, *aolo;
    cudaGetSymbolAddress((void**)&xhi,  g_xhi);
    cudaGetSymbolAddress((void**)&xlo,  g_xlo);
    cudaGetSymbolAddress((void**)&whi,  g_whi);
    cudaGetSymbolAddress((void**)&wlo,  g_wlo);
    cudaGetSymbolAddress((void**)&qhi,  g_qhi);
    cudaGetSymbolAddress((void**)&qlo,  g_qlo);
    cudaGetSymbolAddress((void**)&khi,  g_khi);
    cudaGetSymbolAddress((void**)&klo,  g_klo);
    cudaGetSymbolAddress((void**)&vhi,  g_vhi);
    cudaGetSymbolAddress((void**)&vlo,  g_vlo);
    cudaGetSymbolAddress((void**)&aohi, g_aohi);
    cudaGetSymbolAddress((void**)&aolo, g_aolo);

    const int GEMM_SMEM = NSTAGE * GSTAGE;   // 221184
    cudaFuncSetAttribute(gemm_qkv,
                         cudaFuncAttributeMaxDynamicSharedMemorySize, GEMM_SMEM);
    cudaFuncSetAttribute(gemm_wo,
                         cudaFuncAttributeMaxDynamicSharedMemorySize, GEMM_SMEM);
    cudaFuncSetAttribute(attn_mma,
                         cudaFuncAttributeMaxDynamicSharedMemorySize, AT_SMEM);

    const int NX4 = MM * KK / 4;
    const int NW4 = KK * KK / 4;
    split_fp16<<<NX4 / 256, 256>>>(X, xhi, xlo, NX4);
    dim3 wgrid(NW4 / 256, 1, 4);
    split_w4<<<wgrid, 256>>>(Wq, Wk, Wv, Wo, whi, wlo);

    dim3 qkvgrid(DD / 128, MM / 128, 3);   // 768 CTAs
    gemm_qkv<<<qkvgrid, 256, GEMM_SMEM>>>(xhi, xlo, whi, wlo, bq, bk, bv,
                                          qhi, qlo, khi, klo, vhi, vlo);

    dim3 agrid(TT / 64, HH, BB);           // (32, 16, 2) = 1024 CTAs
    attn_mma<<<agrid, 128, AT_SMEM>>>(F);

    dim3 ogrid(DD / 128, MM / 128);        // (8, 32)
    gemm_wo<<<ogrid, 256, GEMM_SMEM>>>(aohi, aolo, whi + 3*(size_t)KK*KK,
                                       wlo + 3*(size_t)KK*KK, bo, out);
}